// round 3
// baseline (speedup 1.0000x reference)
#include <cuda_runtime.h>
#include <math.h>

#define EMB 768
#define SEQ 2048
#define BATCH 4
#define NHEAD 12
#define HDIM 64
#define FFDIM 3072
#define MROWS (BATCH*SEQ)   // 8192
#define NPROJ 3840          // 5*768 (q,k,v,gate,skip)
#define NCAT  4608          // 6*768 (+ w_o)
#define NBH   (BATCH*NHEAD) // 48

// ---------------- scratch (device globals; no allocation allowed) ----------
__device__ float g_xn    [MROWS*EMB];
__device__ float g_proj  [(size_t)MROWS*NPROJ];
__device__ float g_ctx   [MROWS*EMB];
__device__ float g_attno [MROWS*EMB];
__device__ float g_h     [MROWS*EMB];
__device__ float g_hn    [MROWS*EMB];
__device__ float g_ff1   [(size_t)MROWS*FFDIM];
__device__ float g_wcat  [768*NCAT];
__device__ float g_bcat  [NCAT];
__device__ float g_w1r   [768*FFDIM];
__device__ float g_w2r   [FFDIM*768];
__device__ float g_pm    [(size_t)NBH*16*SEQ];  // partial row max per col-block
__device__ float g_ps    [(size_t)NBH*16*SEQ];  // partial row expsum per col-block
__device__ float g_rowm  [NBH*SEQ];
__device__ float g_rowinv[NBH*SEQ];

// ---------------- helpers ---------------------------------------------------
__device__ __forceinline__ float tf32r(float x) {
    unsigned u;
    asm("cvt.rna.tf32.f32 %0, %1;" : "=r"(u) : "f"(x));
    return __uint_as_float(u);
}

__device__ __forceinline__ void mma_tf32(float (&d)[4], const float (&a)[4], const float (&b)[2]) {
    asm volatile(
        "mma.sync.aligned.m16n8k8.row.col.f32.tf32.tf32.f32 "
        "{%0,%1,%2,%3},{%4,%5,%6,%7},{%8,%9},{%0,%1,%2,%3};\n"
        : "+f"(d[0]), "+f"(d[1]), "+f"(d[2]), "+f"(d[3])
        : "r"(__float_as_uint(a[0])), "r"(__float_as_uint(a[1])),
          "r"(__float_as_uint(a[2])), "r"(__float_as_uint(a[3])),
          "r"(__float_as_uint(b[0])), "r"(__float_as_uint(b[1])));
}

#define CPA(dst, src) asm volatile("cp.async.cg.shared.global [%0], [%1], 16;\n" :: "r"(dst), "l"(src))
#define CPCOMMIT()    asm volatile("cp.async.commit_group;\n" ::: "memory")
#define CPWAIT0()     asm volatile("cp.async.wait_group 0;\n" ::: "memory")

__device__ __forceinline__ float gelu_exact(float v) {
    return 0.5f * v * (1.0f + erff(v * 0.70710678118654752f));
}

// ---------------- weight prep: concat + tf32 round --------------------------
__global__ __launch_bounds__(256) void prep_wcat(
    const float* __restrict__ wq, const float* __restrict__ wk,
    const float* __restrict__ wv, const float* __restrict__ wg,
    const float* __restrict__ ws, const float* __restrict__ wo,
    const float* __restrict__ bq, const float* __restrict__ bk,
    const float* __restrict__ bv, const float* __restrict__ bg,
    const float* __restrict__ bs, const float* __restrict__ bo,
    float* __restrict__ wcat, float* __restrict__ bcat)
{
    int idx = blockIdx.x * 256 + threadIdx.x;
    if (idx < 768 * NCAT) {
        int rr = idx / NCAT, c = idx % NCAT;
        int sel = c / 768, cc = c - sel * 768;
        const float* w = (sel == 0) ? wq : (sel == 1) ? wk : (sel == 2) ? wv
                       : (sel == 3) ? wg : (sel == 4) ? ws : wo;
        wcat[idx] = tf32r(w[rr * 768 + cc]);
    }
    if (idx < NCAT) {
        int sel = idx / 768, cc = idx - sel * 768;
        const float* bb = (sel == 0) ? bq : (sel == 1) ? bk : (sel == 2) ? bv
                        : (sel == 3) ? bg : (sel == 4) ? bs : bo;
        bcat[idx] = bb[cc];
    }
}

__global__ __launch_bounds__(256) void prep_round2(
    const float* __restrict__ s1, float* __restrict__ d1,
    const float* __restrict__ s2, float* __restrict__ d2, int n)
{
    int i = blockIdx.x * 256 + threadIdx.x;
    if (i < n) { d1[i] = tf32r(s1[i]); d2[i] = tf32r(s2[i]); }
}

// ---------------- layernorm (tf32-rounds output) ----------------------------
__global__ __launch_bounds__(256) void ln_kernel(
    const float* __restrict__ x, const float* __restrict__ w,
    const float* __restrict__ b, float* __restrict__ y)
{
    __shared__ float sh[8];
    int t = threadIdx.x;
    const float* xr = x + (size_t)blockIdx.x * EMB;
    float v0 = xr[t], v1 = xr[t + 256], v2 = xr[t + 512];

    float s = v0 + v1 + v2;
    #pragma unroll
    for (int o = 16; o; o >>= 1) s += __shfl_xor_sync(~0u, s, o);
    if ((t & 31) == 0) sh[t >> 5] = s;
    __syncthreads();
    float mean = (sh[0]+sh[1]+sh[2]+sh[3]+sh[4]+sh[5]+sh[6]+sh[7]) * (1.0f/768.0f);
    __syncthreads();

    float d0 = v0 - mean, d1 = v1 - mean, d2 = v2 - mean;
    float q = d0*d0 + d1*d1 + d2*d2;
    #pragma unroll
    for (int o = 16; o; o >>= 1) q += __shfl_xor_sync(~0u, q, o);
    if ((t & 31) == 0) sh[t >> 5] = q;
    __syncthreads();
    float var = (sh[0]+sh[1]+sh[2]+sh[3]+sh[4]+sh[5]+sh[6]+sh[7]) * (1.0f/768.0f);
    float rstd = rsqrtf(var + 1e-5f);

    float* yr = y + (size_t)blockIdx.x * EMB;
    yr[t]       = tf32r(d0 * rstd * w[t]       + b[t]);
    yr[t + 256] = tf32r(d1 * rstd * w[t + 256] + b[t + 256]);
    yr[t + 512] = tf32r(d2 * rstd * w[t + 512] + b[t + 512]);
}

// ---------------- fused gated combine + LN2 ---------------------------------
__global__ __launch_bounds__(256) void combine_ln(
    const float* __restrict__ x, const float* __restrict__ proj,
    const float* __restrict__ attno, const float* __restrict__ w,
    const float* __restrict__ b, float* __restrict__ hout,
    float* __restrict__ hn)
{
    __shared__ float sh[8];
    int t = threadIdx.x;
    size_t row = blockIdx.x;
    const float* xr = x + row * EMB;
    const float* ar = attno + row * EMB;
    const float* gr = proj + row * NPROJ + 2304;
    const float* sr = proj + row * NPROJ + 3072;

    float hv[3];
    #pragma unroll
    for (int i = 0; i < 3; i++) {
        int c = t + i * 256;
        float gg = 1.0f / (1.0f + __expf(-gr[c]));
        hv[i] = xr[c] + gg * ar[c] + (1.0f - gg) * sr[c];
        hout[row * EMB + c] = hv[i];
    }

    float s = hv[0] + hv[1] + hv[2];
    #pragma unroll
    for (int o = 16; o; o >>= 1) s += __shfl_xor_sync(~0u, s, o);
    if ((t & 31) == 0) sh[t >> 5] = s;
    __syncthreads();
    float mean = (sh[0]+sh[1]+sh[2]+sh[3]+sh[4]+sh[5]+sh[6]+sh[7]) * (1.0f/768.0f);
    __syncthreads();

    float d0 = hv[0]-mean, d1 = hv[1]-mean, d2 = hv[2]-mean;
    float q = d0*d0 + d1*d1 + d2*d2;
    #pragma unroll
    for (int o = 16; o; o >>= 1) q += __shfl_xor_sync(~0u, q, o);
    if ((t & 31) == 0) sh[t >> 5] = q;
    __syncthreads();
    float var = (sh[0]+sh[1]+sh[2]+sh[3]+sh[4]+sh[5]+sh[6]+sh[7]) * (1.0f/768.0f);
    float rstd = rsqrtf(var + 1e-5f);

    hn[row * EMB + t]       = tf32r(d0 * rstd * w[t]       + b[t]);
    hn[row * EMB + t + 256] = tf32r(d1 * rstd * w[t + 256] + b[t + 256]);
    hn[row * EMB + t + 512] = tf32r(d2 * rstd * w[t + 512] + b[t + 512]);
}

// ---------------- tf32 tensor-core GEMM 128x128x16 --------------------------
// EPI: 0 bias; 1 bias+tf32round; 2 bias+GELU+tf32round; 3 bias+residual
template <int EPI>
__global__ __launch_bounds__(256, 2) void gemm_tf32(
    const float* __restrict__ A, const float* __restrict__ B,
    const float* __restrict__ bias, const float* __restrict__ R,
    float* __restrict__ C, int M, int N, int K, int ldb)
{
    __shared__ float As[2][128 * 20];
    __shared__ float Bs[2][16 * 136];
    int t = threadIdx.x, lane = t & 31, warp = t >> 5;
    int wm = warp >> 2, wn = warp & 3;
    int g = lane >> 2, r = lane & 3;
    int bm0 = blockIdx.y * 128, bn0 = blockIdx.x * 128;
    int niter = K >> 4;

    float acc[4][4][4];
    #pragma unroll
    for (int i = 0; i < 4; i++)
        #pragma unroll
        for (int j = 0; j < 4; j++)
            #pragma unroll
            for (int q = 0; q < 4; q++) acc[i][j][q] = 0.0f;

    auto issue = [&](int it, int s) {
        int k0 = it << 4;
        unsigned sa = (unsigned)__cvta_generic_to_shared(&As[s][0]);
        unsigned sb = (unsigned)__cvta_generic_to_shared(&Bs[s][0]);
        #pragma unroll
        for (int u = 0; u < 2; u++) {
            int f = t + (u << 8);
            int m = f >> 2, kq = (f & 3) << 2;
            CPA(sa + (unsigned)((m * 20 + kq) << 2),
                A + (size_t)(bm0 + m) * K + k0 + kq);
        }
        #pragma unroll
        for (int u = 0; u < 2; u++) {
            int f = t + (u << 8);
            int kk = f >> 5, nq = (f & 31) << 2;
            CPA(sb + (unsigned)((kk * 136 + nq) << 2),
                B + (size_t)(k0 + kk) * ldb + bn0 + nq);
        }
    };

    issue(0, 0); CPCOMMIT();

    for (int it = 0; it < niter; ++it) {
        CPWAIT0();
        __syncthreads();
        if (it + 1 < niter) issue(it + 1, (it + 1) & 1);
        CPCOMMIT();

        const float* As_ = As[it & 1];
        const float* Bs_ = Bs[it & 1];
        #pragma unroll
        for (int ks = 0; ks < 2; ++ks) {
            int kk = ks << 3;
            float af[4][4], bf[4][2];
            #pragma unroll
            for (int mf = 0; mf < 4; ++mf) {
                int mb = wm * 64 + mf * 16;
                af[mf][0] = As_[(mb + g) * 20 + kk + r];
                af[mf][1] = As_[(mb + 8 + g) * 20 + kk + r];
                af[mf][2] = As_[(mb + g) * 20 + kk + 4 + r];
                af[mf][3] = As_[(mb + 8 + g) * 20 + kk + 4 + r];
            }
            #pragma unroll
            for (int nf = 0; nf < 4; ++nf) {
                int nb = wn * 32 + nf * 8;
                bf[nf][0] = Bs_[(kk + r) * 136 + nb + g];
                bf[nf][1] = Bs_[(kk + 4 + r) * 136 + nb + g];
            }
            #pragma unroll
            for (int mf = 0; mf < 4; ++mf)
                #pragma unroll
                for (int nf = 0; nf < 4; ++nf)
                    mma_tf32(acc[mf][nf], af[mf], bf[nf]);
        }
    }

    #pragma unroll
    for (int mf = 0; mf < 4; ++mf) {
        #pragma unroll
        for (int nf = 0; nf < 4; ++nf) {
            int row = bm0 + wm * 64 + mf * 16 + g;
            int col = bn0 + wn * 32 + nf * 8 + (r << 1);
            float b0 = bias[col], b1 = bias[col + 1];
            float v0 = acc[mf][nf][0] + b0, v1 = acc[mf][nf][1] + b1;
            float v2 = acc[mf][nf][2] + b0, v3 = acc[mf][nf][3] + b1;
            if (EPI == 1) { v0 = tf32r(v0); v1 = tf32r(v1); v2 = tf32r(v2); v3 = tf32r(v3); }
            if (EPI == 2) {
                v0 = tf32r(gelu_exact(v0)); v1 = tf32r(gelu_exact(v1));
                v2 = tf32r(gelu_exact(v2)); v3 = tf32r(gelu_exact(v3));
            }
            if (EPI == 3) {
                const float2 r0 = *(const float2*)(R + (size_t)row * N + col);
                const float2 r1 = *(const float2*)(R + (size_t)(row + 8) * N + col);
                v0 += r0.x; v1 += r0.y; v2 += r1.x; v3 += r1.y;
            }
            *(float2*)(C + (size_t)row * N + col)       = make_float2(v0, v1);
            *(float2*)(C + (size_t)(row + 8) * N + col) = make_float2(v2, v3);
        }
    }
}

// ---------------- QK^T batched + softmax partial stats ----------------------
__global__ __launch_bounds__(256) void qk_tf32(
    const float* __restrict__ proj, float* __restrict__ attw,
    float* __restrict__ pm, float* __restrict__ ps)
{
    int bh = blockIdx.z, b = bh / NHEAD, h = bh % NHEAD;
    const float* Aq = proj + (size_t)b * SEQ * NPROJ + h * HDIM;
    const float* Bk = Aq + 768;
    float* C = attw + (size_t)bh * SEQ * SEQ;

    __shared__ float As[128 * 36];
    __shared__ float Bs[128 * 36];
    __shared__ float sM[4][128];
    __shared__ float sS[4][128];
    int t = threadIdx.x, lane = t & 31, warp = t >> 5;
    int wm = warp >> 2, wn = warp & 3;
    int g = lane >> 2, r = lane & 3;
    int bm0 = blockIdx.y * 128, bn0 = blockIdx.x * 128;

    float acc[4][4][4];
    #pragma unroll
    for (int i = 0; i < 4; i++)
        #pragma unroll
        for (int j = 0; j < 4; j++)
            #pragma unroll
            for (int q = 0; q < 4; q++) acc[i][j][q] = 0.0f;

    #pragma unroll
    for (int ch = 0; ch < 2; ++ch) {
        if (ch) __syncthreads();
        int k0 = ch * 32;
        #pragma unroll
        for (int u = 0; u < 4; u++) {
            int f = t + (u << 8);
            int m = f >> 3, kq = (f & 7) << 2;
            *(float4*)&As[m * 36 + kq] =
                *(const float4*)(Aq + (size_t)(bm0 + m) * NPROJ + k0 + kq);
            *(float4*)&Bs[m * 36 + kq] =
                *(const float4*)(Bk + (size_t)(bn0 + m) * NPROJ + k0 + kq);
        }
        __syncthreads();
        #pragma unroll
        for (int ks = 0; ks < 4; ++ks) {
            int kk = ks << 3;
            float af[4][4], bf[4][2];
            #pragma unroll
            for (int mf = 0; mf < 4; ++mf) {
                int mb = wm * 64 + mf * 16;
                af[mf][0] = As[(mb + g) * 36 + kk + r];
                af[mf][1] = As[(mb + 8 + g) * 36 + kk + r];
                af[mf][2] = As[(mb + g) * 36 + kk + 4 + r];
                af[mf][3] = As[(mb + 8 + g) * 36 + kk + 4 + r];
            }
            #pragma unroll
            for (int nf = 0; nf < 4; ++nf) {
                int nb = wn * 32 + nf * 8;
                bf[nf][0] = Bs[(nb + g) * 36 + kk + r];
                bf[nf][1] = Bs[(nb + g) * 36 + kk + 4 + r];
            }
            #pragma unroll
            for (int mf = 0; mf < 4; ++mf)
                #pragma unroll
                for (int nf = 0; nf < 4; ++nf)
                    mma_tf32(acc[mf][nf], af[mf], bf[nf]);
        }
    }

    // scale in place
    #pragma unroll
    for (int mf = 0; mf < 4; ++mf)
        #pragma unroll
        for (int nf = 0; nf < 4; ++nf)
            #pragma unroll
            for (int q = 0; q < 4; q++) acc[mf][nf][q] *= 0.125f;

    // per-row partial max & expsum (this block's 128 cols)
    #pragma unroll
    for (int mf = 0; mf < 4; ++mf) {
        #pragma unroll
        for (int half = 0; half < 2; ++half) {
            float vv[8];
            #pragma unroll
            for (int nf = 0; nf < 4; ++nf) {
                vv[2*nf]   = acc[mf][nf][2*half];
                vv[2*nf+1] = acc[mf][nf][2*half+1];
            }
            float m = vv[0];
            #pragma unroll
            for (int i = 1; i < 8; i++) m = fmaxf(m, vv[i]);
            m = fmaxf(m, __shfl_xor_sync(~0u, m, 1));
            m = fmaxf(m, __shfl_xor_sync(~0u, m, 2));
            float s = 0.0f;
            #pragma unroll
            for (int i = 0; i < 8; i++) s += __expf(vv[i] - m);
            s += __shfl_xor_sync(~0u, s, 1);
            s += __shfl_xor_sync(~0u, s, 2);
            if (r == 0) {
                int rl = wm * 64 + mf * 16 + half * 8 + g;
                sM[wn][rl] = m; sS[wn][rl] = s;
            }
        }
    }
    __syncthreads();
    if (t < 128) {
        float m0 = sM[0][t], m1 = sM[1][t], m2 = sM[2][t], m3 = sM[3][t];
        float mb = fmaxf(fmaxf(m0, m1), fmaxf(m2, m3));
        float sb = sS[0][t]*__expf(m0-mb) + sS[1][t]*__expf(m1-mb)
                 + sS[2][t]*__expf(m2-mb) + sS[3][t]*__expf(m3-mb);
        size_t pidx = ((size_t)bh * 16 + blockIdx.x) * SEQ + bm0 + t;
        pm[pidx] = mb; ps[pidx] = sb;
    }

    // store raw scaled scores
    #pragma unroll
    for (int mf = 0; mf < 4; ++mf)
        #pragma unroll
        for (int nf = 0; nf < 4; ++nf) {
            int row = bm0 + wm * 64 + mf * 16 + g;
            int col = bn0 + wn * 32 + nf * 8 + (r << 1);
            *(float2*)(C + (size_t)row * SEQ + col) =
                make_float2(acc[mf][nf][0], acc[mf][nf][1]);
            *(float2*)(C + (size_t)(row + 8) * SEQ + col) =
                make_float2(acc[mf][nf][2], acc[mf][nf][3]);
        }
}

// ---------------- softmax stats finalize (one thread per row) ---------------
__global__ __launch_bounds__(256) void softmax_finalize(
    const float* __restrict__ pm, const float* __restrict__ ps,
    float* __restrict__ rowm, float* __restrict__ rowinv)
{
    int i = blockIdx.x * 256 + threadIdx.x;   // i = bh*SEQ + row
    if (i >= NBH * SEQ) return;
    int bh = i / SEQ, row = i - bh * SEQ;
    size_t base = (size_t)bh * 16 * SEQ + row;
    float m = pm[base];
    #pragma unroll
    for (int blk = 1; blk < 16; blk++) m = fmaxf(m, pm[base + (size_t)blk * SEQ]);
    float s = 0.0f;
    #pragma unroll
    for (int blk = 0; blk < 16; blk++)
        s += ps[base + (size_t)blk * SEQ] * __expf(pm[base + (size_t)blk * SEQ] - m);
    rowm[i] = m;
    rowinv[i] = 1.0f / s;
}

// ---------------- PV batched: normalize-on-load, writes attw + ctx ---------
__global__ __launch_bounds__(256) void pv_tf32(
    float* __restrict__ attw, const float* __restrict__ proj,
    const float* __restrict__ rowm, const float* __restrict__ rowinv,
    float* __restrict__ ctx)
{
    int bh = blockIdx.y, b = bh / NHEAD, h = bh % NHEAD;
    float* A = attw + (size_t)bh * SEQ * SEQ;
    const float* V = proj + (size_t)b * SEQ * NPROJ + 1536 + h * HDIM;
    float* Cc = ctx + (size_t)b * SEQ * EMB + h * HDIM;

    __shared__ float As[2][128 * 20];
    __shared__ float Bs[2][16 * 68];
    int t = threadIdx.x, lane = t & 31, warp = t >> 5;
    int wm = warp >> 1, wn = warp & 1;
    int g = lane >> 2, r = lane & 3;
    int bm0 = blockIdx.x * 128;
    const int niter = SEQ / 16;

    // per-thread softmax row constants (each thread transforms 1 fixed row)
    int trow = t >> 1, tc8 = (t & 1) * 8;
    int grow = bm0 + trow;
    float mrow = rowm[bh * SEQ + grow];
    float invr = rowinv[bh * SEQ + grow];

    float acc[2][4][4];
    #pragma unroll
    for (int i = 0; i < 2; i++)
        #pragma unroll
        for (int j = 0; j < 4; j++)
            #pragma unroll
            for (int q = 0; q < 4; q++) acc[i][j][q] = 0.0f;

    auto issue = [&](int it, int s) {
        int k0 = it << 4;
        unsigned sa = (unsigned)__cvta_generic_to_shared(&As[s][0]);
        unsigned sb = (unsigned)__cvta_generic_to_shared(&Bs[s][0]);
        #pragma unroll
        for (int u = 0; u < 2; u++) {
            int f = t + (u << 8);
            int m = f >> 2, kq = (f & 3) << 2;
            CPA(sa + (unsigned)((m * 20 + kq) << 2),
                A + (size_t)(bm0 + m) * SEQ + k0 + kq);
        }
        {
            int kk = t >> 4, nq = (t & 15) << 2;
            CPA(sb + (unsigned)((kk * 68 + nq) << 2),
                V + (size_t)(k0 + kk) * NPROJ + nq);
        }
    };

    issue(0, 0); CPCOMMIT();

    for (int it = 0; it < niter; ++it) {
        CPWAIT0();
        __syncthreads();
        if (it + 1 < niter) issue(it + 1, (it + 1) & 1);
        CPCOMMIT();

        // normalize this buffer's raw scores; write final weights to gmem
        float* As_ = As[it & 1];
        const float* Bs_ = Bs[it & 1];
        {
            int k0 = it << 4;
            float4 u0 = *(float4*)&As_[trow * 20 + tc8];
            float4 u1 = *(float4*)&As_[trow * 20 + tc8 + 4];
            u0.x = __expf(u0.x - mrow) * invr;
            u0.y = __expf(u0.y - mrow) * invr;
            u0.z = __expf(u0.z - mrow) * invr;
            u0.w = __expf(u0.w - mrow) * invr;
            u1.x = __expf(u1.x - mrow) * invr;
            u1.y = __expf(u1.y - mrow) * invr;
            u1.z = __expf(u1.z - mrow) * invr;
            u1.w = __expf(u1.w - mrow) * invr;
            *(float4*)&As_[trow * 20 + tc8]     = u0;
            *(float4*)&As_[trow * 20 + tc8 + 4] = u1;
            *(float4*)(A + (size_t)grow * SEQ + k0 + tc8)     = u0;
            *(float4*)(A + (size_t)grow * SEQ + k0 + tc8 + 4) = u1;
        }
        __syncthreads();

        #pragma unroll
        for (int ks = 0; ks < 2; ++ks) {
            int kk = ks << 3;
            float af[2][4], bf[4][2];
            #pragma unroll
            for (int mf = 0; mf < 2; ++mf) {
                int mb = wm * 32 + mf * 16;
                af[mf][0] = As_[(mb + g) * 20 + kk + r];
                af[mf][1] = As_[(mb + 8 + g) * 20 + kk + r];
                af[mf][2] = As_[(mb + g) * 20 + kk + 4 + r];
                af[mf][3] = As_[(mb + 8 + g) * 20 + kk + 4 + r];
            }
            #pragma unroll
            for (int nf = 0; nf < 4; ++nf) {
                int nb = wn * 32 + nf * 8;
                bf[nf][0] = Bs_[(kk + r) * 68 + nb + g];
                bf[nf][1] = Bs_[(kk + 4 + r) * 68 + nb + g];
            }
            #pragma unroll
            for (int mf = 0; mf < 2; ++mf)
                #pragma unroll
                for (int nf = 0; nf < 4; ++nf)
                    mma_tf32(acc[mf][nf], af[mf], bf[nf]);
        }
    }

    #pragma unroll
    for (int mf = 0; mf < 2; ++mf)
        #pragma unroll
        for (int nf = 0; nf < 4; ++nf) {
            int row = bm0 + wm * 32 + mf * 16 + g;
            int col = wn * 32 + nf * 8 + (r << 1);
            *(float2*)(Cc + (size_t)row * EMB + col) =
                make_float2(tf32r(acc[mf][nf][0]), tf32r(acc[mf][nf][1]));
            *(float2*)(Cc + (size_t)(row + 8) * EMB + col) =
                make_float2(tf32r(acc[mf][nf][2]), tf32r(acc[mf][nf][3]));
        }
}

// ---------------- launcher --------------------------------------------------
extern "C" void kernel_launch(void* const* d_in, const int* in_sizes, int n_in,
                              void* d_out, int out_size)
{
    const float* x      = (const float*)d_in[0];
    const float* ln1_w  = (const float*)d_in[1];
    const float* ln1_b  = (const float*)d_in[2];
    const float* w_q    = (const float*)d_in[3];
    const float* w_k    = (const float*)d_in[4];
    const float* w_v    = (const float*)d_in[5];
    const float* w_o    = (const float*)d_in[6];
    const float* b_q    = (const float*)d_in[7];
    const float* b_k    = (const float*)d_in[8];
    const float* b_v    = (const float*)d_in[9];
    const float* b_o    = (const float*)d_in[10];
    const float* w_gate = (const float*)d_in[11];
    const float* b_gate = (const float*)d_in[12];
    const float* w_skip = (const float*)d_in[13];
    const float* b_skip = (const float*)d_in[14];
    const float* ln2_w  = (const float*)d_in[15];
    const float* ln2_b  = (const float*)d_in[16];
    const float* w1     = (const float*)d_in[17];
    const float* b1     = (const float*)d_in[18];
    const float* w2     = (const float*)d_in[19];
    const float* b2     = (const float*)d_in[20];

    float* out  = (float*)d_out;
    float* attw = out + (size_t)MROWS * EMB;

    float *xn, *proj, *ctx, *attno, *hbuf, *hn, *ff1, *wcat, *bcat, *w1r, *w2r;
    float *pm, *ps, *rowm, *rowinv;
    cudaGetSymbolAddress((void**)&xn,     g_xn);
    cudaGetSymbolAddress((void**)&proj,   g_proj);
    cudaGetSymbolAddress((void**)&ctx,    g_ctx);
    cudaGetSymbolAddress((void**)&attno,  g_attno);
    cudaGetSymbolAddress((void**)&hbuf,   g_h);
    cudaGetSymbolAddress((void**)&hn,     g_hn);
    cudaGetSymbolAddress((void**)&ff1,    g_ff1);
    cudaGetSymbolAddress((void**)&wcat,   g_wcat);
    cudaGetSymbolAddress((void**)&bcat,   g_bcat);
    cudaGetSymbolAddress((void**)&w1r,    g_w1r);
    cudaGetSymbolAddress((void**)&w2r,    g_w2r);
    cudaGetSymbolAddress((void**)&pm,     g_pm);
    cudaGetSymbolAddress((void**)&ps,     g_ps);
    cudaGetSymbolAddress((void**)&rowm,   g_rowm);
    cudaGetSymbolAddress((void**)&rowinv, g_rowinv);

    // 0: attention weight prep
    prep_wcat<<<(768 * NCAT + 255) / 256, 256>>>(
        w_q, w_k, w_v, w_gate, w_skip, w_o,
        b_q, b_k, b_v, b_gate, b_skip, b_o, wcat, bcat);

    // 1: LN1
    ln_kernel<<<MROWS, 256>>>(x, ln1_w, ln1_b, xn);

    // 2: merged q,k,v,gate,skip projection
    gemm_tf32<1><<<dim3(NPROJ / 128, MROWS / 128), 256>>>(
        xn, wcat, bcat, nullptr, proj, MROWS, NPROJ, EMB, NCAT);

    // 3: scores + partial stats
    qk_tf32<<<dim3(SEQ / 128, SEQ / 128, BATCH * NHEAD), 256>>>(proj, attw, pm, ps);

    // 4: finalize row max / inv-sum
    softmax_finalize<<<(NBH * SEQ + 255) / 256, 256>>>(pm, ps, rowm, rowinv);

    // 5: PV with normalize-on-load (also writes final attn weights)
    pv_tf32<<<dim3(SEQ / 128, BATCH * NHEAD), 256>>>(attw, proj, rowm, rowinv, ctx);

    // 6: FFN weight prep (only needed before ff1)
    prep_round2<<<(768 * FFDIM + 255) / 256, 256>>>(w1, w1r, w2, w2r, 768 * FFDIM);

    // 7: output projection
    gemm_tf32<0><<<dim3(EMB / 128, MROWS / 128), 256>>>(
        ctx, wcat + NPROJ, bcat + NPROJ, nullptr, attno, MROWS, EMB, EMB, NCAT);

    // 8: gated combine + LN2 fused
    combine_ln<<<MROWS, 256>>>(x, proj, attno, ln2_w, ln2_b, hbuf, hn);

    // 9-10: FFN
    gemm_tf32<2><<<dim3(FFDIM / 128, MROWS / 128), 256>>>(
        hn, w1r, b1, nullptr, ff1, MROWS, FFDIM, EMB, FFDIM);
    gemm_tf32<3><<<dim3(EMB / 128, MROWS / 128), 256>>>(
        ff1, w2r, b2, hbuf, out, MROWS, EMB, FFDIM, EMB);
}

// round 4
// speedup vs baseline: 1.0225x; 1.0225x over previous
#include <cuda_runtime.h>
#include <math.h>

#define EMB 768
#define SEQ 2048
#define BATCH 4
#define NHEAD 12
#define HDIM 64
#define FFDIM 3072
#define MROWS (BATCH*SEQ)   // 8192
#define NPROJ 3840          // 5*768 (q,k,v,gate,skip)
#define NCAT  4608          // 6*768 (+ w_o)
#define NBH   (BATCH*NHEAD) // 48
#define NKB   32            // 64-col stat blocks per row

// ---------------- scratch (device globals; no allocation allowed) ----------
__device__ float g_xn    [MROWS*EMB];
__device__ float g_proj  [(size_t)MROWS*NPROJ];
__device__ float g_ctx   [MROWS*EMB];
__device__ float g_attno [MROWS*EMB];
__device__ float g_h     [MROWS*EMB];
__device__ float g_hn    [MROWS*EMB];
__device__ float g_ff1   [(size_t)MROWS*FFDIM];
__device__ float g_wcat  [768*NCAT];
__device__ float g_bcat  [NCAT];
__device__ float g_w1r   [768*FFDIM];
__device__ float g_w2r   [FFDIM*768];
__device__ float g_pm    [(size_t)NBH*NKB*SEQ];  // block row max
__device__ float g_ps    [(size_t)NBH*NKB*SEQ];  // block row expsum
__device__ float g_c     [(size_t)NBH*NKB*SEQ];  // per-block softmax scalar

// ---------------- helpers ---------------------------------------------------
__device__ __forceinline__ float tf32r(float x) {
    unsigned u;
    asm("cvt.rna.tf32.f32 %0, %1;" : "=r"(u) : "f"(x));
    return __uint_as_float(u);
}

__device__ __forceinline__ void mma_tf32(float (&d)[4], const float (&a)[4], const float (&b)[2]) {
    asm volatile(
        "mma.sync.aligned.m16n8k8.row.col.f32.tf32.tf32.f32 "
        "{%0,%1,%2,%3},{%4,%5,%6,%7},{%8,%9},{%0,%1,%2,%3};\n"
        : "+f"(d[0]), "+f"(d[1]), "+f"(d[2]), "+f"(d[3])
        : "r"(__float_as_uint(a[0])), "r"(__float_as_uint(a[1])),
          "r"(__float_as_uint(a[2])), "r"(__float_as_uint(a[3])),
          "r"(__float_as_uint(b[0])), "r"(__float_as_uint(b[1])));
}

#define CPA(dst, src) asm volatile("cp.async.cg.shared.global [%0], [%1], 16;\n" :: "r"(dst), "l"(src))
#define CPCOMMIT()    asm volatile("cp.async.commit_group;\n" ::: "memory")
#define CPWAIT0()     asm volatile("cp.async.wait_group 0;\n" ::: "memory")

__device__ __forceinline__ float gelu_exact(float v) {
    return 0.5f * v * (1.0f + erff(v * 0.70710678118654752f));
}

// ---------------- weight prep: concat + tf32 round --------------------------
__global__ __launch_bounds__(256) void prep_wcat(
    const float* __restrict__ wq, const float* __restrict__ wk,
    const float* __restrict__ wv, const float* __restrict__ wg,
    const float* __restrict__ ws, const float* __restrict__ wo,
    const float* __restrict__ bq, const float* __restrict__ bk,
    const float* __restrict__ bv, const float* __restrict__ bg,
    const float* __restrict__ bs, const float* __restrict__ bo,
    float* __restrict__ wcat, float* __restrict__ bcat)
{
    int idx = blockIdx.x * 256 + threadIdx.x;
    if (idx < 768 * NCAT) {
        int rr = idx / NCAT, c = idx % NCAT;
        int sel = c / 768, cc = c - sel * 768;
        const float* w = (sel == 0) ? wq : (sel == 1) ? wk : (sel == 2) ? wv
                       : (sel == 3) ? wg : (sel == 4) ? ws : wo;
        wcat[idx] = tf32r(w[rr * 768 + cc]);
    }
    if (idx < NCAT) {
        int sel = idx / 768, cc = idx - sel * 768;
        const float* bb = (sel == 0) ? bq : (sel == 1) ? bk : (sel == 2) ? bv
                        : (sel == 3) ? bg : (sel == 4) ? bs : bo;
        bcat[idx] = bb[cc];
    }
}

__global__ __launch_bounds__(256) void prep_round2(
    const float* __restrict__ s1, float* __restrict__ d1,
    const float* __restrict__ s2, float* __restrict__ d2, int n)
{
    int i = blockIdx.x * 256 + threadIdx.x;
    if (i < n) { d1[i] = tf32r(s1[i]); d2[i] = tf32r(s2[i]); }
}

// ---------------- layernorm (tf32-rounds output) ----------------------------
__global__ __launch_bounds__(256) void ln_kernel(
    const float* __restrict__ x, const float* __restrict__ w,
    const float* __restrict__ b, float* __restrict__ y)
{
    __shared__ float sh[8];
    int t = threadIdx.x;
    const float* xr = x + (size_t)blockIdx.x * EMB;
    float v0 = xr[t], v1 = xr[t + 256], v2 = xr[t + 512];

    float s = v0 + v1 + v2;
    #pragma unroll
    for (int o = 16; o; o >>= 1) s += __shfl_xor_sync(~0u, s, o);
    if ((t & 31) == 0) sh[t >> 5] = s;
    __syncthreads();
    float mean = (sh[0]+sh[1]+sh[2]+sh[3]+sh[4]+sh[5]+sh[6]+sh[7]) * (1.0f/768.0f);
    __syncthreads();

    float d0 = v0 - mean, d1 = v1 - mean, d2 = v2 - mean;
    float q = d0*d0 + d1*d1 + d2*d2;
    #pragma unroll
    for (int o = 16; o; o >>= 1) q += __shfl_xor_sync(~0u, q, o);
    if ((t & 31) == 0) sh[t >> 5] = q;
    __syncthreads();
    float var = (sh[0]+sh[1]+sh[2]+sh[3]+sh[4]+sh[5]+sh[6]+sh[7]) * (1.0f/768.0f);
    float rstd = rsqrtf(var + 1e-5f);

    float* yr = y + (size_t)blockIdx.x * EMB;
    yr[t]       = tf32r(d0 * rstd * w[t]       + b[t]);
    yr[t + 256] = tf32r(d1 * rstd * w[t + 256] + b[t + 256]);
    yr[t + 512] = tf32r(d2 * rstd * w[t + 512] + b[t + 512]);
}

// ---------------- fused gated combine + LN2 ---------------------------------
__global__ __launch_bounds__(256) void combine_ln(
    const float* __restrict__ x, const float* __restrict__ proj,
    const float* __restrict__ attno, const float* __restrict__ w,
    const float* __restrict__ b, float* __restrict__ hout,
    float* __restrict__ hn)
{
    __shared__ float sh[8];
    int t = threadIdx.x;
    size_t row = blockIdx.x;
    const float* xr = x + row * EMB;
    const float* ar = attno + row * EMB;
    const float* gr = proj + row * NPROJ + 2304;
    const float* sr = proj + row * NPROJ + 3072;

    float hv[3];
    #pragma unroll
    for (int i = 0; i < 3; i++) {
        int c = t + i * 256;
        float gg = 1.0f / (1.0f + __expf(-gr[c]));
        hv[i] = xr[c] + gg * ar[c] + (1.0f - gg) * sr[c];
        hout[row * EMB + c] = hv[i];
    }

    float s = hv[0] + hv[1] + hv[2];
    #pragma unroll
    for (int o = 16; o; o >>= 1) s += __shfl_xor_sync(~0u, s, o);
    if ((t & 31) == 0) sh[t >> 5] = s;
    __syncthreads();
    float mean = (sh[0]+sh[1]+sh[2]+sh[3]+sh[4]+sh[5]+sh[6]+sh[7]) * (1.0f/768.0f);
    __syncthreads();

    float d0 = hv[0]-mean, d1 = hv[1]-mean, d2 = hv[2]-mean;
    float q = d0*d0 + d1*d1 + d2*d2;
    #pragma unroll
    for (int o = 16; o; o >>= 1) q += __shfl_xor_sync(~0u, q, o);
    if ((t & 31) == 0) sh[t >> 5] = q;
    __syncthreads();
    float var = (sh[0]+sh[1]+sh[2]+sh[3]+sh[4]+sh[5]+sh[6]+sh[7]) * (1.0f/768.0f);
    float rstd = rsqrtf(var + 1e-5f);

    hn[row * EMB + t]       = tf32r(d0 * rstd * w[t]       + b[t]);
    hn[row * EMB + t + 256] = tf32r(d1 * rstd * w[t + 256] + b[t + 256]);
    hn[row * EMB + t + 512] = tf32r(d2 * rstd * w[t + 512] + b[t + 512]);
}

// ---------------- tf32 tensor-core GEMM 128x128x16 --------------------------
// EPI: 0 bias; 1 bias+tf32round; 2 bias+GELU+tf32round; 3 bias+residual
template <int EPI>
__global__ __launch_bounds__(256, 2) void gemm_tf32(
    const float* __restrict__ A, const float* __restrict__ B,
    const float* __restrict__ bias, const float* __restrict__ R,
    float* __restrict__ C, int M, int N, int K, int ldb)
{
    __shared__ float As[2][128 * 20];
    __shared__ float Bs[2][16 * 136];
    int t = threadIdx.x, lane = t & 31, warp = t >> 5;
    int wm = warp >> 2, wn = warp & 3;
    int g = lane >> 2, r = lane & 3;
    int bm0 = blockIdx.y * 128, bn0 = blockIdx.x * 128;
    int niter = K >> 4;

    float acc[4][4][4];
    #pragma unroll
    for (int i = 0; i < 4; i++)
        #pragma unroll
        for (int j = 0; j < 4; j++)
            #pragma unroll
            for (int q = 0; q < 4; q++) acc[i][j][q] = 0.0f;

    auto issue = [&](int it, int s) {
        int k0 = it << 4;
        unsigned sa = (unsigned)__cvta_generic_to_shared(&As[s][0]);
        unsigned sb = (unsigned)__cvta_generic_to_shared(&Bs[s][0]);
        #pragma unroll
        for (int u = 0; u < 2; u++) {
            int f = t + (u << 8);
            int m = f >> 2, kq = (f & 3) << 2;
            CPA(sa + (unsigned)((m * 20 + kq) << 2),
                A + (size_t)(bm0 + m) * K + k0 + kq);
        }
        #pragma unroll
        for (int u = 0; u < 2; u++) {
            int f = t + (u << 8);
            int kk = f >> 5, nq = (f & 31) << 2;
            CPA(sb + (unsigned)((kk * 136 + nq) << 2),
                B + (size_t)(k0 + kk) * ldb + bn0 + nq);
        }
    };

    issue(0, 0); CPCOMMIT();

    for (int it = 0; it < niter; ++it) {
        CPWAIT0();
        __syncthreads();
        if (it + 1 < niter) issue(it + 1, (it + 1) & 1);
        CPCOMMIT();

        const float* As_ = As[it & 1];
        const float* Bs_ = Bs[it & 1];
        #pragma unroll
        for (int ks = 0; ks < 2; ++ks) {
            int kk = ks << 3;
            float af[4][4], bf[4][2];
            #pragma unroll
            for (int mf = 0; mf < 4; ++mf) {
                int mb = wm * 64 + mf * 16;
                af[mf][0] = As_[(mb + g) * 20 + kk + r];
                af[mf][1] = As_[(mb + 8 + g) * 20 + kk + r];
                af[mf][2] = As_[(mb + g) * 20 + kk + 4 + r];
                af[mf][3] = As_[(mb + 8 + g) * 20 + kk + 4 + r];
            }
            #pragma unroll
            for (int nf = 0; nf < 4; ++nf) {
                int nb = wn * 32 + nf * 8;
                bf[nf][0] = Bs_[(kk + r) * 136 + nb + g];
                bf[nf][1] = Bs_[(kk + 4 + r) * 136 + nb + g];
            }
            #pragma unroll
            for (int mf = 0; mf < 4; ++mf)
                #pragma unroll
                for (int nf = 0; nf < 4; ++nf)
                    mma_tf32(acc[mf][nf], af[mf], bf[nf]);
        }
    }

    #pragma unroll
    for (int mf = 0; mf < 4; ++mf) {
        #pragma unroll
        for (int nf = 0; nf < 4; ++nf) {
            int row = bm0 + wm * 64 + mf * 16 + g;
            int col = bn0 + wn * 32 + nf * 8 + (r << 1);
            float b0 = bias[col], b1 = bias[col + 1];
            float v0 = acc[mf][nf][0] + b0, v1 = acc[mf][nf][1] + b1;
            float v2 = acc[mf][nf][2] + b0, v3 = acc[mf][nf][3] + b1;
            if (EPI == 1) { v0 = tf32r(v0); v1 = tf32r(v1); v2 = tf32r(v2); v3 = tf32r(v3); }
            if (EPI == 2) {
                v0 = tf32r(gelu_exact(v0)); v1 = tf32r(gelu_exact(v1));
                v2 = tf32r(gelu_exact(v2)); v3 = tf32r(gelu_exact(v3));
            }
            if (EPI == 3) {
                const float2 r0 = *(const float2*)(R + (size_t)row * N + col);
                const float2 r1 = *(const float2*)(R + (size_t)(row + 8) * N + col);
                v0 += r0.x; v1 += r0.y; v2 += r1.x; v3 += r1.y;
            }
            *(float2*)(C + (size_t)row * N + col)       = make_float2(v0, v1);
            *(float2*)(C + (size_t)(row + 8) * N + col) = make_float2(v2, v3);
        }
    }
}

// ---------------- QK^T 128x64 tiles; writes e=exp(s-m_blk) + stats ----------
__global__ __launch_bounds__(256, 2) void qk_tf32(
    const float* __restrict__ proj, float* __restrict__ attw,
    float* __restrict__ pm, float* __restrict__ ps)
{
    int bh = blockIdx.z, b = bh / NHEAD, h = bh % NHEAD;
    const float* Aq = proj + (size_t)b * SEQ * NPROJ + h * HDIM;
    const float* Bk = Aq + 768;
    float* C = attw + (size_t)bh * SEQ * SEQ;

    __shared__ float As[128 * 36];
    __shared__ float Bs[64 * 36];
    __shared__ float sM[2][128];
    __shared__ float sS[2][128];
    int t = threadIdx.x, lane = t & 31, warp = t >> 5;
    int wm = warp >> 1, wn = warp & 1;
    int g = lane >> 2, r = lane & 3;
    int bm0 = blockIdx.y * 128, bn0 = blockIdx.x * 64;

    float acc[2][4][4];
    #pragma unroll
    for (int i = 0; i < 2; i++)
        #pragma unroll
        for (int j = 0; j < 4; j++)
            #pragma unroll
            for (int q = 0; q < 4; q++) acc[i][j][q] = 0.0f;

    #pragma unroll
    for (int ch = 0; ch < 2; ++ch) {
        if (ch) __syncthreads();
        int k0 = ch * 32;
        #pragma unroll
        for (int u = 0; u < 4; u++) {
            int f = t + (u << 8);
            int m = f >> 3, kq = (f & 7) << 2;
            *(float4*)&As[m * 36 + kq] =
                *(const float4*)(Aq + (size_t)(bm0 + m) * NPROJ + k0 + kq);
        }
        #pragma unroll
        for (int u = 0; u < 2; u++) {
            int f = t + (u << 8);
            int m = f >> 3, kq = (f & 7) << 2;
            *(float4*)&Bs[m * 36 + kq] =
                *(const float4*)(Bk + (size_t)(bn0 + m) * NPROJ + k0 + kq);
        }
        __syncthreads();
        #pragma unroll
        for (int ks = 0; ks < 4; ++ks) {
            int kk = ks << 3;
            float af[2][4], bf[4][2];
            #pragma unroll
            for (int mf = 0; mf < 2; ++mf) {
                int mb = wm * 32 + mf * 16;
                af[mf][0] = As[(mb + g) * 36 + kk + r];
                af[mf][1] = As[(mb + 8 + g) * 36 + kk + r];
                af[mf][2] = As[(mb + g) * 36 + kk + 4 + r];
                af[mf][3] = As[(mb + 8 + g) * 36 + kk + 4 + r];
            }
            #pragma unroll
            for (int nf = 0; nf < 4; ++nf) {
                int nb = wn * 32 + nf * 8;
                bf[nf][0] = Bs[(nb + g) * 36 + kk + r];
                bf[nf][1] = Bs[(nb + g) * 36 + kk + 4 + r];
            }
            #pragma unroll
            for (int mf = 0; mf < 2; ++mf)
                #pragma unroll
                for (int nf = 0; nf < 4; ++nf)
                    mma_tf32(acc[mf][nf], af[mf], bf[nf]);
        }
    }

    // scale 1/8
    #pragma unroll
    for (int mf = 0; mf < 2; ++mf)
        #pragma unroll
        for (int nf = 0; nf < 4; ++nf)
            #pragma unroll
            for (int q = 0; q < 4; q++) acc[mf][nf][q] *= 0.125f;

    // per-row max over this warp's 32 cols
    #pragma unroll
    for (int mf = 0; mf < 2; ++mf) {
        #pragma unroll
        for (int half = 0; half < 2; ++half) {
            float m = acc[mf][0][2*half];
            #pragma unroll
            for (int nf = 0; nf < 4; ++nf) {
                m = fmaxf(m, acc[mf][nf][2*half]);
                m = fmaxf(m, acc[mf][nf][2*half+1]);
            }
            m = fmaxf(m, __shfl_xor_sync(~0u, m, 1));
            m = fmaxf(m, __shfl_xor_sync(~0u, m, 2));
            if (r == 0) sM[wn][wm*32 + mf*16 + half*8 + g] = m;
        }
    }
    __syncthreads();

    // exp in place + per-row sums
    #pragma unroll
    for (int mf = 0; mf < 2; ++mf) {
        #pragma unroll
        for (int half = 0; half < 2; ++half) {
            int rl = wm*32 + mf*16 + half*8 + g;
            float m = fmaxf(sM[0][rl], sM[1][rl]);
            float s = 0.0f;
            #pragma unroll
            for (int nf = 0; nf < 4; ++nf) {
                float e0 = __expf(acc[mf][nf][2*half]   - m);
                float e1 = __expf(acc[mf][nf][2*half+1] - m);
                acc[mf][nf][2*half] = e0; acc[mf][nf][2*half+1] = e1;
                s += e0 + e1;
            }
            s += __shfl_xor_sync(~0u, s, 1);
            s += __shfl_xor_sync(~0u, s, 2);
            if (r == 0) sS[wn][rl] = s;
        }
    }
    __syncthreads();

    if (t < 128) {
        size_t pidx = ((size_t)bh * NKB + blockIdx.x) * SEQ + bm0 + t;
        pm[pidx] = fmaxf(sM[0][t], sM[1][t]);
        ps[pidx] = sS[0][t] + sS[1][t];
    }

    // store e
    #pragma unroll
    for (int mf = 0; mf < 2; ++mf)
        #pragma unroll
        for (int nf = 0; nf < 4; ++nf) {
            int row = bm0 + wm * 32 + mf * 16 + g;
            int col = bn0 + wn * 32 + nf * 8 + (r << 1);
            *(float2*)(C + (size_t)row * SEQ + col) =
                make_float2(acc[mf][nf][0], acc[mf][nf][1]);
            *(float2*)(C + (size_t)(row + 8) * SEQ + col) =
                make_float2(acc[mf][nf][2], acc[mf][nf][3]);
        }
}

// ---------------- finalize: per-row, per-block scalar c ---------------------
__global__ __launch_bounds__(256) void softmax_finalize(
    const float* __restrict__ pm, const float* __restrict__ ps,
    float* __restrict__ cc)
{
    int i = blockIdx.x * 256 + threadIdx.x;
    if (i >= NBH * SEQ) return;
    int bh = i / SEQ, row = i - bh * SEQ;
    size_t base = (size_t)bh * NKB * SEQ + row;

    float pmv[NKB];
    float m = -1e30f;
    #pragma unroll
    for (int blk = 0; blk < NKB; blk++) {
        pmv[blk] = pm[base + (size_t)blk * SEQ];
        m = fmaxf(m, pmv[blk]);
    }
    float ev[NKB], sum = 0.0f;
    #pragma unroll
    for (int blk = 0; blk < NKB; blk++) {
        ev[blk] = __expf(pmv[blk] - m);
        sum += ps[base + (size_t)blk * SEQ] * ev[blk];
    }
    float inv = 1.0f / sum;
    #pragma unroll
    for (int blk = 0; blk < NKB; blk++)
        cc[base + (size_t)blk * SEQ] = ev[blk] * inv;
}

// ---------------- PV: raw-e MMA with c-scaled fragments; writes weights ----
__global__ __launch_bounds__(256, 2) void pv_tf32(
    float* __restrict__ attw, const float* __restrict__ proj,
    const float* __restrict__ cc, float* __restrict__ ctx)
{
    int bh = blockIdx.y, b = bh / NHEAD, h = bh % NHEAD;
    float* A = attw + (size_t)bh * SEQ * SEQ;
    const float* V = proj + (size_t)b * SEQ * NPROJ + 1536 + h * HDIM;
    float* Cc = ctx + (size_t)b * SEQ * EMB + h * HDIM;
    const float* cbh = cc + (size_t)bh * NKB * SEQ;

    __shared__ float As[2][128 * 20];
    __shared__ float Bs[2][16 * 68];
    int t = threadIdx.x, lane = t & 31, warp = t >> 5;
    int wm = warp >> 1, wn = warp & 1;
    int g = lane >> 2, r = lane & 3;
    int bm0 = blockIdx.x * 128;
    const int niter = SEQ / 16;

    int trow = t >> 1, tc8 = (t & 1) * 8;
    int grow = bm0 + trow;

    float acc[2][4][4];
    #pragma unroll
    for (int i = 0; i < 2; i++)
        #pragma unroll
        for (int j = 0; j < 4; j++)
            #pragma unroll
            for (int q = 0; q < 4; q++) acc[i][j][q] = 0.0f;

    auto issue = [&](int it, int s) {
        int k0 = it << 4;
        unsigned sa = (unsigned)__cvta_generic_to_shared(&As[s][0]);
        unsigned sb = (unsigned)__cvta_generic_to_shared(&Bs[s][0]);
        #pragma unroll
        for (int u = 0; u < 2; u++) {
            int f = t + (u << 8);
            int m = f >> 2, kq = (f & 3) << 2;
            CPA(sa + (unsigned)((m * 20 + kq) << 2),
                A + (size_t)(bm0 + m) * SEQ + k0 + kq);
        }
        {
            int kk = t >> 4, nq = (t & 15) << 2;
            CPA(sb + (unsigned)((kk * 68 + nq) << 2),
                V + (size_t)(k0 + kk) * NPROJ + nq);
        }
    };

    issue(0, 0); CPCOMMIT();

    float cfa[2][2], cst = 0.0f;

    for (int it = 0; it < niter; ++it) {
        CPWAIT0();
        __syncthreads();
        if (it + 1 < niter) issue(it + 1, (it + 1) & 1);
        CPCOMMIT();

        float* As_ = As[it & 1];
        const float* Bs_ = Bs[it & 1];

        if ((it & 3) == 0) {
            int kb = it >> 2;
            const float* cblk = cbh + (size_t)kb * SEQ;
            cst = cblk[grow];
            cfa[0][0] = cblk[bm0 + wm*32 + g];
            cfa[0][1] = cblk[bm0 + wm*32 + 8 + g];
            cfa[1][0] = cblk[bm0 + wm*32 + 16 + g];
            cfa[1][1] = cblk[bm0 + wm*32 + 24 + g];
        }

        // stream final weights w = e * c to gmem (no extra sync needed)
        {
            int k0 = it << 4;
            float4 u0 = *(float4*)&As_[trow * 20 + tc8];
            float4 u1 = *(float4*)&As_[trow * 20 + tc8 + 4];
            u0.x *= cst; u0.y *= cst; u0.z *= cst; u0.w *= cst;
            u1.x *= cst; u1.y *= cst; u1.z *= cst; u1.w *= cst;
            *(float4*)(A + (size_t)grow * SEQ + k0 + tc8)     = u0;
            *(float4*)(A + (size_t)grow * SEQ + k0 + tc8 + 4) = u1;
        }

        #pragma unroll
        for (int ks = 0; ks < 2; ++ks) {
            int kk = ks << 3;
            float af[2][4], bf[4][2];
            #pragma unroll
            for (int mf = 0; mf < 2; ++mf) {
                int mb = wm * 32 + mf * 16;
                af[mf][0] = As_[(mb + g) * 20 + kk + r]     * cfa[mf][0];
                af[mf][1] = As_[(mb + 8 + g) * 20 + kk + r] * cfa[mf][1];
                af[mf][2] = As_[(mb + g) * 20 + kk + 4 + r]     * cfa[mf][0];
                af[mf][3] = As_[(mb + 8 + g) * 20 + kk + 4 + r] * cfa[mf][1];
            }
            #pragma unroll
            for (int nf = 0; nf < 4; ++nf) {
                int nb = wn * 32 + nf * 8;
                bf[nf][0] = Bs_[(kk + r) * 68 + nb + g];
                bf[nf][1] = Bs_[(kk + 4 + r) * 68 + nb + g];
            }
            #pragma unroll
            for (int mf = 0; mf < 2; ++mf)
                #pragma unroll
                for (int nf = 0; nf < 4; ++nf)
                    mma_tf32(acc[mf][nf], af[mf], bf[nf]);
        }
    }

    #pragma unroll
    for (int mf = 0; mf < 2; ++mf)
        #pragma unroll
        for (int nf = 0; nf < 4; ++nf) {
            int row = bm0 + wm * 32 + mf * 16 + g;
            int col = wn * 32 + nf * 8 + (r << 1);
            *(float2*)(Cc + (size_t)row * EMB + col) =
                make_float2(tf32r(acc[mf][nf][0]), tf32r(acc[mf][nf][1]));
            *(float2*)(Cc + (size_t)(row + 8) * EMB + col) =
                make_float2(tf32r(acc[mf][nf][2]), tf32r(acc[mf][nf][3]));
        }
}

// ---------------- launcher --------------------------------------------------
extern "C" void kernel_launch(void* const* d_in, const int* in_sizes, int n_in,
                              void* d_out, int out_size)
{
    const float* x      = (const float*)d_in[0];
    const float* ln1_w  = (const float*)d_in[1];
    const float* ln1_b  = (const float*)d_in[2];
    const float* w_q    = (const float*)d_in[3];
    const float* w_k    = (const float*)d_in[4];
    const float* w_v    = (const float*)d_in[5];
    const float* w_o    = (const float*)d_in[6];
    const float* b_q    = (const float*)d_in[7];
    const float* b_k    = (const float*)d_in[8];
    const float* b_v    = (const float*)d_in[9];
    const float* b_o    = (const float*)d_in[10];
    const float* w_gate = (const float*)d_in[11];
    const float* b_gate = (const float*)d_in[12];
    const float* w_skip = (const float*)d_in[13];
    const float* b_skip = (const float*)d_in[14];
    const float* ln2_w  = (const float*)d_in[15];
    const float* ln2_b  = (const float*)d_in[16];
    const float* w1     = (const float*)d_in[17];
    const float* b1     = (const float*)d_in[18];
    const float* w2     = (const float*)d_in[19];
    const float* b2     = (const float*)d_in[20];

    float* out  = (float*)d_out;
    float* attw = out + (size_t)MROWS * EMB;

    float *xn, *proj, *ctx, *attno, *hbuf, *hn, *ff1, *wcat, *bcat, *w1r, *w2r;
    float *pm, *ps, *cc;
    cudaGetSymbolAddress((void**)&xn,    g_xn);
    cudaGetSymbolAddress((void**)&proj,  g_proj);
    cudaGetSymbolAddress((void**)&ctx,   g_ctx);
    cudaGetSymbolAddress((void**)&attno, g_attno);
    cudaGetSymbolAddress((void**)&hbuf,  g_h);
    cudaGetSymbolAddress((void**)&hn,    g_hn);
    cudaGetSymbolAddress((void**)&ff1,   g_ff1);
    cudaGetSymbolAddress((void**)&wcat,  g_wcat);
    cudaGetSymbolAddress((void**)&bcat,  g_bcat);
    cudaGetSymbolAddress((void**)&w1r,   g_w1r);
    cudaGetSymbolAddress((void**)&w2r,   g_w2r);
    cudaGetSymbolAddress((void**)&pm,    g_pm);
    cudaGetSymbolAddress((void**)&ps,    g_ps);
    cudaGetSymbolAddress((void**)&cc,    g_c);

    prep_wcat<<<(768 * NCAT + 255) / 256, 256>>>(
        w_q, w_k, w_v, w_gate, w_skip, w_o,
        b_q, b_k, b_v, b_gate, b_skip, b_o, wcat, bcat);

    ln_kernel<<<MROWS, 256>>>(x, ln1_w, ln1_b, xn);

    gemm_tf32<1><<<dim3(NPROJ / 128, MROWS / 128), 256>>>(
        xn, wcat, bcat, nullptr, proj, MROWS, NPROJ, EMB, NCAT);

    qk_tf32<<<dim3(SEQ / 64, SEQ / 128, NBH), 256>>>(proj, attw, pm, ps);
    softmax_finalize<<<(NBH * SEQ + 255) / 256, 256>>>(pm, ps, cc);
    pv_tf32<<<dim3(SEQ / 128, NBH), 256>>>(attw, proj, cc, ctx);

    prep_round2<<<(768 * FFDIM + 255) / 256, 256>>>(w1, w1r, w2, w2r, 768 * FFDIM);

    gemm_tf32<0><<<dim3(EMB / 128, MROWS / 128), 256>>>(
        ctx, wcat + NPROJ, bcat + NPROJ, nullptr, attno, MROWS, EMB, EMB, NCAT);

    combine_ln<<<MROWS, 256>>>(x, proj, attno, ln2_w, ln2_b, hbuf, hn);

    gemm_tf32<2><<<dim3(FFDIM / 128, MROWS / 128), 256>>>(
        hn, w1r, b1, nullptr, ff1, MROWS, FFDIM, EMB, FFDIM);
    gemm_tf32<3><<<dim3(EMB / 128, MROWS / 128), 256>>>(
        ff1, w2r, b2, hbuf, out, MROWS, EMB, FFDIM, EMB);
}

// round 5
// speedup vs baseline: 1.1325x; 1.1075x over previous
#include <cuda_runtime.h>
#include <math.h>

#define EMB 768
#define SEQ 2048
#define BATCH 4
#define NHEAD 12
#define HDIM 64
#define FFDIM 3072
#define MROWS (BATCH*SEQ)   // 8192
#define NPROJ 3840          // 5*768 (q,k,v,gate,skip)
#define NCAT  4608          // 6*768 (+ w_o)
#define NBH   (BATCH*NHEAD) // 48

// ---------------- scratch (device globals; no allocation allowed) ----------
__device__ float g_xn    [MROWS*EMB];
__device__ float g_proj  [(size_t)MROWS*NPROJ];
__device__ float g_ctx   [MROWS*EMB];
__device__ float g_attno [MROWS*EMB];
__device__ float g_h     [MROWS*EMB];
__device__ float g_hn    [MROWS*EMB];
__device__ float g_ff1   [(size_t)MROWS*FFDIM];
__device__ float g_wcat  [768*NCAT];
__device__ float g_bcat  [NCAT];
__device__ float g_w1r   [768*FFDIM];
__device__ float g_w2r   [FFDIM*768];

// ---------------- helpers ---------------------------------------------------
__device__ __forceinline__ float tf32r(float x) {
    unsigned u;
    asm("cvt.rna.tf32.f32 %0, %1;" : "=r"(u) : "f"(x));
    return __uint_as_float(u);
}

__device__ __forceinline__ void mma_tf32(float (&d)[4], const float (&a)[4], const float (&b)[2]) {
    asm volatile(
        "mma.sync.aligned.m16n8k8.row.col.f32.tf32.tf32.f32 "
        "{%0,%1,%2,%3},{%4,%5,%6,%7},{%8,%9},{%0,%1,%2,%3};\n"
        : "+f"(d[0]), "+f"(d[1]), "+f"(d[2]), "+f"(d[3])
        : "r"(__float_as_uint(a[0])), "r"(__float_as_uint(a[1])),
          "r"(__float_as_uint(a[2])), "r"(__float_as_uint(a[3])),
          "r"(__float_as_uint(b[0])), "r"(__float_as_uint(b[1])));
}

#define CPA(dst, src) asm volatile("cp.async.cg.shared.global [%0], [%1], 16;\n" :: "r"(dst), "l"(src))
#define CPCOMMIT()    asm volatile("cp.async.commit_group;\n" ::: "memory")
#define CPWAIT0()     asm volatile("cp.async.wait_group 0;\n" ::: "memory")

__device__ __forceinline__ float gelu_exact(float v) {
    return 0.5f * v * (1.0f + erff(v * 0.70710678118654752f));
}

// ---------------- weight prep: concat + tf32 round (q pre-scaled 1/8) ------
__global__ __launch_bounds__(256) void prep_wcat(
    const float* __restrict__ wq, const float* __restrict__ wk,
    const float* __restrict__ wv, const float* __restrict__ wg,
    const float* __restrict__ ws, const float* __restrict__ wo,
    const float* __restrict__ bq, const float* __restrict__ bk,
    const float* __restrict__ bv, const float* __restrict__ bg,
    const float* __restrict__ bs, const float* __restrict__ bo,
    float* __restrict__ wcat, float* __restrict__ bcat)
{
    int idx = blockIdx.x * 256 + threadIdx.x;
    if (idx < 768 * NCAT) {
        int rr = idx / NCAT, c = idx % NCAT;
        int sel = c / 768, cc = c - sel * 768;
        const float* w = (sel == 0) ? wq : (sel == 1) ? wk : (sel == 2) ? wv
                       : (sel == 3) ? wg : (sel == 4) ? ws : wo;
        float sc = (sel == 0) ? 0.125f : 1.0f;
        wcat[idx] = tf32r(w[rr * 768 + cc] * sc);
    }
    if (idx < NCAT) {
        int sel = idx / 768, cc = idx - sel * 768;
        const float* bb = (sel == 0) ? bq : (sel == 1) ? bk : (sel == 2) ? bv
                        : (sel == 3) ? bg : (sel == 4) ? bs : bo;
        float sc = (sel == 0) ? 0.125f : 1.0f;
        bcat[idx] = bb[cc] * sc;
    }
}

__global__ __launch_bounds__(256) void prep_round2(
    const float* __restrict__ s1, float* __restrict__ d1,
    const float* __restrict__ s2, float* __restrict__ d2, int n)
{
    int i = blockIdx.x * 256 + threadIdx.x;
    if (i < n) { d1[i] = tf32r(s1[i]); d2[i] = tf32r(s2[i]); }
}

// ---------------- layernorm (tf32-rounds output) ----------------------------
__global__ __launch_bounds__(256) void ln_kernel(
    const float* __restrict__ x, const float* __restrict__ w,
    const float* __restrict__ b, float* __restrict__ y)
{
    __shared__ float sh[8];
    int t = threadIdx.x;
    const float* xr = x + (size_t)blockIdx.x * EMB;
    float v0 = xr[t], v1 = xr[t + 256], v2 = xr[t + 512];

    float s = v0 + v1 + v2;
    #pragma unroll
    for (int o = 16; o; o >>= 1) s += __shfl_xor_sync(~0u, s, o);
    if ((t & 31) == 0) sh[t >> 5] = s;
    __syncthreads();
    float mean = (sh[0]+sh[1]+sh[2]+sh[3]+sh[4]+sh[5]+sh[6]+sh[7]) * (1.0f/768.0f);
    __syncthreads();

    float d0 = v0 - mean, d1 = v1 - mean, d2 = v2 - mean;
    float q = d0*d0 + d1*d1 + d2*d2;
    #pragma unroll
    for (int o = 16; o; o >>= 1) q += __shfl_xor_sync(~0u, q, o);
    if ((t & 31) == 0) sh[t >> 5] = q;
    __syncthreads();
    float var = (sh[0]+sh[1]+sh[2]+sh[3]+sh[4]+sh[5]+sh[6]+sh[7]) * (1.0f/768.0f);
    float rstd = rsqrtf(var + 1e-5f);

    float* yr = y + (size_t)blockIdx.x * EMB;
    yr[t]       = tf32r(d0 * rstd * w[t]       + b[t]);
    yr[t + 256] = tf32r(d1 * rstd * w[t + 256] + b[t + 256]);
    yr[t + 512] = tf32r(d2 * rstd * w[t + 512] + b[t + 512]);
}

// ---------------- fused gated combine + LN2 ---------------------------------
__global__ __launch_bounds__(256) void combine_ln(
    const float* __restrict__ x, const float* __restrict__ proj,
    const float* __restrict__ attno, const float* __restrict__ w,
    const float* __restrict__ b, float* __restrict__ hout,
    float* __restrict__ hn)
{
    __shared__ float sh[8];
    int t = threadIdx.x;
    size_t row = blockIdx.x;
    const float* xr = x + row * EMB;
    const float* ar = attno + row * EMB;
    const float* gr = proj + row * NPROJ + 2304;
    const float* sr = proj + row * NPROJ + 3072;

    float hv[3];
    #pragma unroll
    for (int i = 0; i < 3; i++) {
        int c = t + i * 256;
        float gg = 1.0f / (1.0f + __expf(-gr[c]));
        hv[i] = xr[c] + gg * ar[c] + (1.0f - gg) * sr[c];
        hout[row * EMB + c] = hv[i];
    }

    float s = hv[0] + hv[1] + hv[2];
    #pragma unroll
    for (int o = 16; o; o >>= 1) s += __shfl_xor_sync(~0u, s, o);
    if ((t & 31) == 0) sh[t >> 5] = s;
    __syncthreads();
    float mean = (sh[0]+sh[1]+sh[2]+sh[3]+sh[4]+sh[5]+sh[6]+sh[7]) * (1.0f/768.0f);
    __syncthreads();

    float d0 = hv[0]-mean, d1 = hv[1]-mean, d2 = hv[2]-mean;
    float q = d0*d0 + d1*d1 + d2*d2;
    #pragma unroll
    for (int o = 16; o; o >>= 1) q += __shfl_xor_sync(~0u, q, o);
    if ((t & 31) == 0) sh[t >> 5] = q;
    __syncthreads();
    float var = (sh[0]+sh[1]+sh[2]+sh[3]+sh[4]+sh[5]+sh[6]+sh[7]) * (1.0f/768.0f);
    float rstd = rsqrtf(var + 1e-5f);

    hn[row * EMB + t]       = tf32r(d0 * rstd * w[t]       + b[t]);
    hn[row * EMB + t + 256] = tf32r(d1 * rstd * w[t + 256] + b[t + 256]);
    hn[row * EMB + t + 512] = tf32r(d2 * rstd * w[t + 512] + b[t + 512]);
}

// ---------------- tf32 tensor-core GEMM 128x128x16 --------------------------
// EPI: 0 bias; 1 bias+tf32round; 2 bias+GELU+tf32round; 3 bias+residual
template <int EPI>
__global__ __launch_bounds__(256, 2) void gemm_tf32(
    const float* __restrict__ A, const float* __restrict__ B,
    const float* __restrict__ bias, const float* __restrict__ R,
    float* __restrict__ C, int M, int N, int K, int ldb)
{
    __shared__ float As[2][128 * 20];
    __shared__ float Bs[2][16 * 136];
    int t = threadIdx.x, lane = t & 31, warp = t >> 5;
    int wm = warp >> 2, wn = warp & 3;
    int g = lane >> 2, r = lane & 3;
    int bm0 = blockIdx.y * 128, bn0 = blockIdx.x * 128;
    int niter = K >> 4;

    float acc[4][4][4];
    #pragma unroll
    for (int i = 0; i < 4; i++)
        #pragma unroll
        for (int j = 0; j < 4; j++)
            #pragma unroll
            for (int q = 0; q < 4; q++) acc[i][j][q] = 0.0f;

    auto issue = [&](int it, int s) {
        int k0 = it << 4;
        unsigned sa = (unsigned)__cvta_generic_to_shared(&As[s][0]);
        unsigned sb = (unsigned)__cvta_generic_to_shared(&Bs[s][0]);
        #pragma unroll
        for (int u = 0; u < 2; u++) {
            int f = t + (u << 8);
            int m = f >> 2, kq = (f & 3) << 2;
            CPA(sa + (unsigned)((m * 20 + kq) << 2),
                A + (size_t)(bm0 + m) * K + k0 + kq);
        }
        #pragma unroll
        for (int u = 0; u < 2; u++) {
            int f = t + (u << 8);
            int kk = f >> 5, nq = (f & 31) << 2;
            CPA(sb + (unsigned)((kk * 136 + nq) << 2),
                B + (size_t)(k0 + kk) * ldb + bn0 + nq);
        }
    };

    issue(0, 0); CPCOMMIT();

    for (int it = 0; it < niter; ++it) {
        CPWAIT0();
        __syncthreads();
        if (it + 1 < niter) issue(it + 1, (it + 1) & 1);
        CPCOMMIT();

        const float* As_ = As[it & 1];
        const float* Bs_ = Bs[it & 1];
        #pragma unroll
        for (int ks = 0; ks < 2; ++ks) {
            int kk = ks << 3;
            float af[4][4], bf[4][2];
            #pragma unroll
            for (int mf = 0; mf < 4; ++mf) {
                int mb = wm * 64 + mf * 16;
                af[mf][0] = As_[(mb + g) * 20 + kk + r];
                af[mf][1] = As_[(mb + 8 + g) * 20 + kk + r];
                af[mf][2] = As_[(mb + g) * 20 + kk + 4 + r];
                af[mf][3] = As_[(mb + 8 + g) * 20 + kk + 4 + r];
            }
            #pragma unroll
            for (int nf = 0; nf < 4; ++nf) {
                int nb = wn * 32 + nf * 8;
                bf[nf][0] = Bs_[(kk + r) * 136 + nb + g];
                bf[nf][1] = Bs_[(kk + 4 + r) * 136 + nb + g];
            }
            #pragma unroll
            for (int mf = 0; mf < 4; ++mf)
                #pragma unroll
                for (int nf = 0; nf < 4; ++nf)
                    mma_tf32(acc[mf][nf], af[mf], bf[nf]);
        }
    }

    #pragma unroll
    for (int mf = 0; mf < 4; ++mf) {
        #pragma unroll
        for (int nf = 0; nf < 4; ++nf) {
            int row = bm0 + wm * 64 + mf * 16 + g;
            int col = bn0 + wn * 32 + nf * 8 + (r << 1);
            float b0 = bias[col], b1 = bias[col + 1];
            float v0 = acc[mf][nf][0] + b0, v1 = acc[mf][nf][1] + b1;
            float v2 = acc[mf][nf][2] + b0, v3 = acc[mf][nf][3] + b1;
            if (EPI == 1) { v0 = tf32r(v0); v1 = tf32r(v1); v2 = tf32r(v2); v3 = tf32r(v3); }
            if (EPI == 2) {
                v0 = tf32r(gelu_exact(v0)); v1 = tf32r(gelu_exact(v1));
                v2 = tf32r(gelu_exact(v2)); v3 = tf32r(gelu_exact(v3));
            }
            if (EPI == 3) {
                const float2 r0 = *(const float2*)(R + (size_t)row * N + col);
                const float2 r1 = *(const float2*)(R + (size_t)(row + 8) * N + col);
                v0 += r0.x; v1 += r0.y; v2 += r1.x; v3 += r1.y;
            }
            *(float2*)(C + (size_t)row * N + col)       = make_float2(v0, v1);
            *(float2*)(C + (size_t)(row + 8) * N + col) = make_float2(v2, v3);
        }
    }
}

// ---------------- fused flash-style attention (2-pass recompute) ------------
// CTA: 128 rows of one (b,h). Warp owns 16 full rows -> stats in registers.
// Pass1: online (m,l). Pass2: recompute S, write w=exp(s-m)/l once, PV via shfl.
__global__ __launch_bounds__(256, 2) void attn_fused(
    const float* __restrict__ proj, float* __restrict__ attw,
    float* __restrict__ ctx)
{
    extern __shared__ float smem[];
    float* Qs  = smem;                    // 128 x 68
    float* Ks0 = Qs  + 128 * 68;          // 64 x 68
    float* Ks1 = Ks0 + 64 * 68;
    float* Vs0 = Ks1 + 64 * 68;           // 64 x 72
    float* Vs1 = Vs0 + 64 * 72;

    int bh = blockIdx.y, b = bh / NHEAD, h = bh % NHEAD;
    const float* Qp = proj + (size_t)b * SEQ * NPROJ + h * HDIM;
    const float* Kp = Qp + 768;
    const float* Vp = Qp + 1536;
    float* Wo = attw + (size_t)bh * SEQ * SEQ;
    float* Cc = ctx + (size_t)b * SEQ * EMB + h * HDIM;

    int t = threadIdx.x, lane = t & 31, warp = t >> 5;
    int g = lane >> 2, r = lane & 3;
    int wrow = warp * 16;
    int bm0 = blockIdx.x * 128;

    auto issueK = [&](int it, int s) {
        unsigned sk = (unsigned)__cvta_generic_to_shared(s ? Ks1 : Ks0);
        #pragma unroll
        for (int u = 0; u < 4; u++) {
            int idx = t + (u << 8);
            int kr = idx >> 4, c4 = (idx & 15) << 2;
            CPA(sk + (unsigned)((kr * 68 + c4) << 2),
                Kp + (size_t)(it * 64 + kr) * NPROJ + c4);
        }
    };
    auto issueV = [&](int it, int s) {
        unsigned sv = (unsigned)__cvta_generic_to_shared(s ? Vs1 : Vs0);
        #pragma unroll
        for (int u = 0; u < 4; u++) {
            int idx = t + (u << 8);
            int kr = idx >> 4, c4 = (idx & 15) << 2;
            CPA(sv + (unsigned)((kr * 72 + c4) << 2),
                Vp + (size_t)(it * 64 + kr) * NPROJ + c4);
        }
    };

    // load Q once (rows bm0..bm0+128)
    {
        unsigned sq = (unsigned)__cvta_generic_to_shared(Qs);
        #pragma unroll
        for (int u = 0; u < 8; u++) {
            int idx = t + (u << 8);
            int qr = idx >> 4, c4 = (idx & 15) << 2;
            CPA(sq + (unsigned)((qr * 68 + c4) << 2),
                Qp + (size_t)(bm0 + qr) * NPROJ + c4);
        }
    }
    issueK(0, 0); CPCOMMIT();

    float mh[2] = {-1e30f, -1e30f};
    float lh[2] = {0.0f, 0.0f};

    // ---------------- pass 1: online stats ----------------
    for (int it = 0; it < SEQ / 64; ++it) {
        CPWAIT0();
        __syncthreads();
        if (it + 1 < SEQ / 64) issueK(it + 1, (it + 1) & 1);
        CPCOMMIT();

        const float* Kb = (it & 1) ? Ks1 : Ks0;
        float acc[8][4];
        #pragma unroll
        for (int nf = 0; nf < 8; nf++)
            #pragma unroll
            for (int q = 0; q < 4; q++) acc[nf][q] = 0.0f;

        #pragma unroll
        for (int ks = 0; ks < 8; ks++) {
            int kk = ks << 3;
            float af[4];
            af[0] = Qs[(wrow + g) * 68 + kk + r];
            af[1] = Qs[(wrow + 8 + g) * 68 + kk + r];
            af[2] = Qs[(wrow + g) * 68 + kk + 4 + r];
            af[3] = Qs[(wrow + 8 + g) * 68 + kk + 4 + r];
            #pragma unroll
            for (int nf = 0; nf < 8; nf++) {
                float bf[2];
                bf[0] = Kb[(nf * 8 + g) * 68 + kk + r];
                bf[1] = Kb[(nf * 8 + g) * 68 + kk + 4 + r];
                mma_tf32(acc[nf], af, bf);
            }
        }

        #pragma unroll
        for (int half = 0; half < 2; half++) {
            float mb = -1e30f;
            #pragma unroll
            for (int nf = 0; nf < 8; nf++)
                mb = fmaxf(mb, fmaxf(acc[nf][2*half], acc[nf][2*half+1]));
            mb = fmaxf(mb, __shfl_xor_sync(~0u, mb, 1));
            mb = fmaxf(mb, __shfl_xor_sync(~0u, mb, 2));
            float mn = fmaxf(mh[half], mb);
            float ss = 0.0f;
            #pragma unroll
            for (int nf = 0; nf < 8; nf++)
                ss += __expf(acc[nf][2*half] - mn) + __expf(acc[nf][2*half+1] - mn);
            ss += __shfl_xor_sync(~0u, ss, 1);
            ss += __shfl_xor_sync(~0u, ss, 2);
            lh[half] = lh[half] * __expf(mh[half] - mn) + ss;
            mh[half] = mn;
        }
    }

    float invl[2] = {1.0f / lh[0], 1.0f / lh[1]};

    float acco[8][4];
    #pragma unroll
    for (int nf = 0; nf < 8; nf++)
        #pragma unroll
        for (int q = 0; q < 4; q++) acco[nf][q] = 0.0f;

    issueK(0, 0); issueV(0, 0); CPCOMMIT();

    // ---------------- pass 2: recompute, write w, PV ----------------
    for (int it = 0; it < SEQ / 64; ++it) {
        CPWAIT0();
        __syncthreads();
        if (it + 1 < SEQ / 64) { issueK(it + 1, (it + 1) & 1); issueV(it + 1, (it + 1) & 1); }
        CPCOMMIT();

        const float* Kb = (it & 1) ? Ks1 : Ks0;
        const float* Vb = (it & 1) ? Vs1 : Vs0;
        float acc[8][4];
        #pragma unroll
        for (int nf = 0; nf < 8; nf++)
            #pragma unroll
            for (int q = 0; q < 4; q++) acc[nf][q] = 0.0f;

        #pragma unroll
        for (int ks = 0; ks < 8; ks++) {
            int kk = ks << 3;
            float af[4];
            af[0] = Qs[(wrow + g) * 68 + kk + r];
            af[1] = Qs[(wrow + 8 + g) * 68 + kk + r];
            af[2] = Qs[(wrow + g) * 68 + kk + 4 + r];
            af[3] = Qs[(wrow + 8 + g) * 68 + kk + 4 + r];
            #pragma unroll
            for (int nf = 0; nf < 8; nf++) {
                float bf[2];
                bf[0] = Kb[(nf * 8 + g) * 68 + kk + r];
                bf[1] = Kb[(nf * 8 + g) * 68 + kk + 4 + r];
                mma_tf32(acc[nf], af, bf);
            }
        }

        // normalize to final weights in regs
        #pragma unroll
        for (int nf = 0; nf < 8; nf++) {
            acc[nf][0] = __expf(acc[nf][0] - mh[0]) * invl[0];
            acc[nf][1] = __expf(acc[nf][1] - mh[0]) * invl[0];
            acc[nf][2] = __expf(acc[nf][2] - mh[1]) * invl[1];
            acc[nf][3] = __expf(acc[nf][3] - mh[1]) * invl[1];
        }

        // store final attention weights (only write of attw)
        {
            size_t ro0 = (size_t)(bm0 + wrow + g) * SEQ + it * 64;
            size_t ro1 = ro0 + (size_t)8 * SEQ;
            #pragma unroll
            for (int nf = 0; nf < 8; nf++) {
                *(float2*)(Wo + ro0 + nf * 8 + 2 * r) = make_float2(acc[nf][0], acc[nf][1]);
                *(float2*)(Wo + ro1 + nf * 8 + 2 * r) = make_float2(acc[nf][2], acc[nf][3]);
            }
        }

        // PV: build A-fragments from w-registers via shfl, MMA with V tile
        int src0 = (g << 2) + (r >> 1);
        int src2 = src0 + 2;
        bool odd = (r & 1);
        #pragma unroll
        for (int ks = 0; ks < 8; ks++) {
            float v00 = __shfl_sync(~0u, acc[ks][0], src0);
            float v01 = __shfl_sync(~0u, acc[ks][1], src0);
            float v20 = __shfl_sync(~0u, acc[ks][2], src0);
            float v21 = __shfl_sync(~0u, acc[ks][3], src0);
            float u00 = __shfl_sync(~0u, acc[ks][0], src2);
            float u01 = __shfl_sync(~0u, acc[ks][1], src2);
            float u20 = __shfl_sync(~0u, acc[ks][2], src2);
            float u21 = __shfl_sync(~0u, acc[ks][3], src2);
            float a[4];
            a[0] = odd ? v01 : v00;
            a[1] = odd ? v21 : v20;
            a[2] = odd ? u01 : u00;
            a[3] = odd ? u21 : u20;
            #pragma unroll
            for (int nf = 0; nf < 8; nf++) {
                float bf[2];
                bf[0] = Vb[(ks * 8 + r) * 72 + nf * 8 + g];
                bf[1] = Vb[(ks * 8 + 4 + r) * 72 + nf * 8 + g];
                mma_tf32(acco[nf], a, bf);
            }
        }
    }

    // write context (tf32-rounded: input of w_o GEMM)
    #pragma unroll
    for (int nf = 0; nf < 8; nf++) {
        int col = nf * 8 + 2 * r;
        *(float2*)(Cc + (size_t)(bm0 + wrow + g) * EMB + col) =
            make_float2(tf32r(acco[nf][0]), tf32r(acco[nf][1]));
        *(float2*)(Cc + (size_t)(bm0 + wrow + 8 + g) * EMB + col) =
            make_float2(tf32r(acco[nf][2]), tf32r(acco[nf][3]));
    }
}

#define ATTN_SMEM ((128*68 + 2*64*68 + 2*64*72) * 4)

// ---------------- launcher --------------------------------------------------
extern "C" void kernel_launch(void* const* d_in, const int* in_sizes, int n_in,
                              void* d_out, int out_size)
{
    const float* x      = (const float*)d_in[0];
    const float* ln1_w  = (const float*)d_in[1];
    const float* ln1_b  = (const float*)d_in[2];
    const float* w_q    = (const float*)d_in[3];
    const float* w_k    = (const float*)d_in[4];
    const float* w_v    = (const float*)d_in[5];
    const float* w_o    = (const float*)d_in[6];
    const float* b_q    = (const float*)d_in[7];
    const float* b_k    = (const float*)d_in[8];
    const float* b_v    = (const float*)d_in[9];
    const float* b_o    = (const float*)d_in[10];
    const float* w_gate = (const float*)d_in[11];
    const float* b_gate = (const float*)d_in[12];
    const float* w_skip = (const float*)d_in[13];
    const float* b_skip = (const float*)d_in[14];
    const float* ln2_w  = (const float*)d_in[15];
    const float* ln2_b  = (const float*)d_in[16];
    const float* w1     = (const float*)d_in[17];
    const float* b1     = (const float*)d_in[18];
    const float* w2     = (const float*)d_in[19];
    const float* b2     = (const float*)d_in[20];

    float* out  = (float*)d_out;
    float* attw = out + (size_t)MROWS * EMB;

    float *xn, *proj, *ctx, *attno, *hbuf, *hn, *ff1, *wcat, *bcat, *w1r, *w2r;
    cudaGetSymbolAddress((void**)&xn,    g_xn);
    cudaGetSymbolAddress((void**)&proj,  g_proj);
    cudaGetSymbolAddress((void**)&ctx,   g_ctx);
    cudaGetSymbolAddress((void**)&attno, g_attno);
    cudaGetSymbolAddress((void**)&hbuf,  g_h);
    cudaGetSymbolAddress((void**)&hn,    g_hn);
    cudaGetSymbolAddress((void**)&ff1,   g_ff1);
    cudaGetSymbolAddress((void**)&wcat,  g_wcat);
    cudaGetSymbolAddress((void**)&bcat,  g_bcat);
    cudaGetSymbolAddress((void**)&w1r,   g_w1r);
    cudaGetSymbolAddress((void**)&w2r,   g_w2r);

    cudaFuncSetAttribute(attn_fused,
                         cudaFuncAttributeMaxDynamicSharedMemorySize, ATTN_SMEM);

    prep_wcat<<<(768 * NCAT + 255) / 256, 256>>>(
        w_q, w_k, w_v, w_gate, w_skip, w_o,
        b_q, b_k, b_v, b_gate, b_skip, b_o, wcat, bcat);

    ln_kernel<<<MROWS, 256>>>(x, ln1_w, ln1_b, xn);

    gemm_tf32<1><<<dim3(NPROJ / 128, MROWS / 128), 256>>>(
        xn, wcat, bcat, nullptr, proj, MROWS, NPROJ, EMB, NCAT);

    attn_fused<<<dim3(SEQ / 128, NBH), 256, ATTN_SMEM>>>(proj, attw, ctx);

    prep_round2<<<(768 * FFDIM + 255) / 256, 256>>>(w1, w1r, w2, w2r, 768 * FFDIM);

    gemm_tf32<0><<<dim3(EMB / 128, MROWS / 128), 256>>>(
        ctx, wcat + NPROJ, bcat + NPROJ, nullptr, attno, MROWS, EMB, EMB, NCAT);

    combine_ln<<<MROWS, 256>>>(x, proj, attno, ln2_w, ln2_b, hbuf, hn);

    gemm_tf32<2><<<dim3(FFDIM / 128, MROWS / 128), 256>>>(
        hn, w1r, b1, nullptr, ff1, MROWS, FFDIM, EMB, FFDIM);
    gemm_tf32<3><<<dim3(EMB / 128, MROWS / 128), 256>>>(
        ff1, w2r, b2, hbuf, out, MROWS, EMB, FFDIM, EMB);
}

// round 6
// speedup vs baseline: 2.1192x; 1.8712x over previous
#include <cuda_runtime.h>
#include <cuda_fp16.h>
#include <math.h>

#define EMB 768
#define SEQ 2048
#define BATCH 4
#define NHEAD 12
#define HDIM 64
#define FFDIM 3072
#define MROWS (BATCH*SEQ)   // 8192
#define NPROJ 3840
#define NCAT  4608
#define NQKV  2304
#define NGS   1536
#define NBH   (BATCH*NHEAD)

// ---------------- scratch (device globals) ----------------------------------
__device__ __half g_xnh  [MROWS*EMB];
__device__ __half g_qkvh [(size_t)MROWS*NQKV];
__device__ float  g_gs   [(size_t)MROWS*NGS];
__device__ __half g_ctxh [MROWS*EMB];
__device__ float  g_attno[MROWS*EMB];
__device__ float  g_h    [MROWS*EMB];
__device__ __half g_hnh  [MROWS*EMB];
__device__ __half g_ff1h [(size_t)MROWS*FFDIM];
__device__ __half g_wcatT[(size_t)NCAT*EMB];
__device__ float  g_bcat [NCAT];
__device__ __half g_w1T  [(size_t)FFDIM*EMB];
__device__ __half g_w2T  [(size_t)EMB*FFDIM];

// ---------------- helpers ----------------------------------------------------
__device__ __forceinline__ unsigned smem_u32(const void* p) {
    unsigned a;
    asm("{ .reg .u64 t; cvta.to.shared.u64 t, %1; cvt.u32.u64 %0, t; }" : "=r"(a) : "l"(p));
    return a;
}
__device__ __forceinline__ void mma_f16(float (&d)[4], const unsigned (&a)[4],
                                        unsigned b0, unsigned b1) {
    asm volatile(
        "mma.sync.aligned.m16n8k16.row.col.f32.f16.f16.f32 "
        "{%0,%1,%2,%3},{%4,%5,%6,%7},{%8,%9},{%0,%1,%2,%3};\n"
        : "+f"(d[0]), "+f"(d[1]), "+f"(d[2]), "+f"(d[3])
        : "r"(a[0]), "r"(a[1]), "r"(a[2]), "r"(a[3]), "r"(b0), "r"(b1));
}
#define LDMX4(R, addr) \
    asm volatile("ldmatrix.sync.aligned.m8n8.x4.shared.b16 {%0,%1,%2,%3}, [%4];" \
        : "=r"((R)[0]), "=r"((R)[1]), "=r"((R)[2]), "=r"((R)[3]) : "r"(addr))
#define LDMX4T(R, addr) \
    asm volatile("ldmatrix.sync.aligned.m8n8.x4.trans.shared.b16 {%0,%1,%2,%3}, [%4];" \
        : "=r"((R)[0]), "=r"((R)[1]), "=r"((R)[2]), "=r"((R)[3]) : "r"(addr))
#define CPA(dst, src) asm volatile("cp.async.cg.shared.global [%0], [%1], 16;\n" :: "r"(dst), "l"(src))
#define CPCOMMIT()    asm volatile("cp.async.commit_group;\n" ::: "memory")
#define CPWAIT0()     asm volatile("cp.async.wait_group 0;\n" ::: "memory")

__device__ __forceinline__ unsigned f22h(float lo, float hi) {
    unsigned u;
    asm("cvt.rn.f16x2.f32 %0, %1, %2;" : "=r"(u) : "f"(hi), "f"(lo));
    return u;
}
__device__ __forceinline__ float gelu_exact(float v) {
    return 0.5f * v * (1.0f + erff(v * 0.70710678118654752f));
}

// ---------------- weight prep ------------------------------------------------
// wcatT[n][k] = w_sel[k][n%768] (q scaled 1/8), half
__global__ __launch_bounds__(256) void prep_wcat_t(
    const float* __restrict__ wq, const float* __restrict__ wk,
    const float* __restrict__ wv, const float* __restrict__ wg,
    const float* __restrict__ ws, const float* __restrict__ wo,
    __half* __restrict__ dst)
{
    __shared__ float tile[32][33];
    int bx = blockIdx.x << 5;   // over NCAT
    int by = blockIdx.y << 5;   // over 768 (k)
    int tx = threadIdx.x & 31, ty = threadIdx.x >> 5;
    int sel = bx / 768, cc0 = bx - sel * 768;
    const float* w = (sel == 0) ? wq : (sel == 1) ? wk : (sel == 2) ? wv
                   : (sel == 3) ? wg : (sel == 4) ? ws : wo;
    float sc = (sel == 0) ? 0.125f : 1.0f;
    #pragma unroll
    for (int i = 0; i < 32; i += 8)
        tile[ty + i][tx] = w[(size_t)(by + ty + i) * 768 + cc0 + tx] * sc;
    __syncthreads();
    #pragma unroll
    for (int i = 0; i < 32; i += 8)
        dst[(size_t)(bx + ty + i) * 768 + by + tx] = __float2half_rn(tile[tx][ty + i]);
}

__global__ __launch_bounds__(256) void prep_bcat(
    const float* __restrict__ bq, const float* __restrict__ bk,
    const float* __restrict__ bv, const float* __restrict__ bg,
    const float* __restrict__ bs, const float* __restrict__ bo,
    float* __restrict__ bcat)
{
    int idx = blockIdx.x * 256 + threadIdx.x;
    if (idx >= NCAT) return;
    int sel = idx / 768, cc = idx - sel * 768;
    const float* bb = (sel == 0) ? bq : (sel == 1) ? bk : (sel == 2) ? bv
                    : (sel == 3) ? bg : (sel == 4) ? bs : bo;
    bcat[idx] = bb[cc] * ((sel == 0) ? 0.125f : 1.0f);
}

// dst[n][k] = src[k][n], half.  grid(N/32, K/32)
__global__ __launch_bounds__(256) void transpose_cvt(
    const float* __restrict__ src, __half* __restrict__ dst, int K, int N)
{
    __shared__ float tile[32][33];
    int bx = blockIdx.x << 5, by = blockIdx.y << 5;
    int tx = threadIdx.x & 31, ty = threadIdx.x >> 5;
    #pragma unroll
    for (int i = 0; i < 32; i += 8)
        tile[ty + i][tx] = src[(size_t)(by + ty + i) * N + bx + tx];
    __syncthreads();
    #pragma unroll
    for (int i = 0; i < 32; i += 8)
        dst[(size_t)(bx + ty + i) * K + by + tx] = __float2half_rn(tile[tx][ty + i]);
}

// ---------------- layernorm → half ------------------------------------------
__global__ __launch_bounds__(256) void ln_kernel(
    const float* __restrict__ x, const float* __restrict__ w,
    const float* __restrict__ b, __half* __restrict__ y)
{
    __shared__ float sh[8];
    int t = threadIdx.x;
    const float* xr = x + (size_t)blockIdx.x * EMB;
    float2 v01 = *(const float2*)(xr + 2 * t);
    float v2 = xr[512 + t];

    float s = v01.x + v01.y + v2;
    #pragma unroll
    for (int o = 16; o; o >>= 1) s += __shfl_xor_sync(~0u, s, o);
    if ((t & 31) == 0) sh[t >> 5] = s;
    __syncthreads();
    float mean = (sh[0]+sh[1]+sh[2]+sh[3]+sh[4]+sh[5]+sh[6]+sh[7]) * (1.0f/768.0f);
    __syncthreads();

    float d0 = v01.x - mean, d1 = v01.y - mean, d2 = v2 - mean;
    float q = d0*d0 + d1*d1 + d2*d2;
    #pragma unroll
    for (int o = 16; o; o >>= 1) q += __shfl_xor_sync(~0u, q, o);
    if ((t & 31) == 0) sh[t >> 5] = q;
    __syncthreads();
    float var = (sh[0]+sh[1]+sh[2]+sh[3]+sh[4]+sh[5]+sh[6]+sh[7]) * (1.0f/768.0f);
    float rstd = rsqrtf(var + 1e-5f);

    float2 w01 = *(const float2*)(w + 2 * t);
    float2 b01 = *(const float2*)(b + 2 * t);
    __half* yr = y + (size_t)blockIdx.x * EMB;
    *(__half2*)(yr + 2 * t) =
        __floats2half2_rn(d0 * rstd * w01.x + b01.x, d1 * rstd * w01.y + b01.y);
    yr[512 + t] = __float2half_rn(d2 * rstd * w[512 + t] + b[512 + t]);
}

// ---------------- fused gated combine + LN2 ---------------------------------
__global__ __launch_bounds__(256) void combine_ln(
    const float* __restrict__ x, const float* __restrict__ gs,
    const float* __restrict__ attno, const float* __restrict__ w,
    const float* __restrict__ b, float* __restrict__ hout,
    __half* __restrict__ hn)
{
    __shared__ float sh[8];
    int t = threadIdx.x;
    size_t row = blockIdx.x;
    const float* xr = x + row * EMB;
    const float* ar = attno + row * EMB;
    const float* gsr = gs + row * NGS;

    float2 x01 = *(const float2*)(xr + 2*t);      float x2 = xr[512 + t];
    float2 a01 = *(const float2*)(ar + 2*t);      float a2 = ar[512 + t];
    float2 g01 = *(const float2*)(gsr + 2*t);     float g2 = gsr[512 + t];
    float2 s01 = *(const float2*)(gsr + 768 + 2*t); float s2 = gsr[768 + 512 + t];

    float gg0 = 1.0f / (1.0f + __expf(-g01.x));
    float gg1 = 1.0f / (1.0f + __expf(-g01.y));
    float gg2 = 1.0f / (1.0f + __expf(-g2));
    float hv0 = x01.x + gg0 * a01.x + (1.0f - gg0) * s01.x;
    float hv1 = x01.y + gg1 * a01.y + (1.0f - gg1) * s01.y;
    float hv2 = x2 + gg2 * a2 + (1.0f - gg2) * s2;

    *(float2*)(hout + row * EMB + 2*t) = make_float2(hv0, hv1);
    hout[row * EMB + 512 + t] = hv2;

    float s = hv0 + hv1 + hv2;
    #pragma unroll
    for (int o = 16; o; o >>= 1) s += __shfl_xor_sync(~0u, s, o);
    if ((t & 31) == 0) sh[t >> 5] = s;
    __syncthreads();
    float mean = (sh[0]+sh[1]+sh[2]+sh[3]+sh[4]+sh[5]+sh[6]+sh[7]) * (1.0f/768.0f);
    __syncthreads();

    float d0 = hv0-mean, d1 = hv1-mean, d2 = hv2-mean;
    float q = d0*d0 + d1*d1 + d2*d2;
    #pragma unroll
    for (int o = 16; o; o >>= 1) q += __shfl_xor_sync(~0u, q, o);
    if ((t & 31) == 0) sh[t >> 5] = q;
    __syncthreads();
    float var = (sh[0]+sh[1]+sh[2]+sh[3]+sh[4]+sh[5]+sh[6]+sh[7]) * (1.0f/768.0f);
    float rstd = rsqrtf(var + 1e-5f);

    float2 w01 = *(const float2*)(w + 2*t);
    float2 b01 = *(const float2*)(b + 2*t);
    __half* hr = hn + row * EMB;
    *(__half2*)(hr + 2*t) =
        __floats2half2_rn(d0 * rstd * w01.x + b01.x, d1 * rstd * w01.y + b01.y);
    hr[512 + t] = __float2half_rn(d2 * rstd * w[512 + t] + b[512 + t]);
}

// ---------------- fp16 tensor-core GEMM 128x128x32 --------------------------
// A[M,K] half row-major, Bt[N,K] half row-major (pre-transposed weights)
// EPI: 0 bias->fp32 C0; 2 bias+GELU->half C0; 3 bias+R->fp32 C0;
//      4 bias, split: col<2304 half->C0(ldc 2304), else fp32->C1(ldc 1536)
template <int EPI>
__global__ __launch_bounds__(256, 2) void gemm_f16(
    const __half* __restrict__ A, const __half* __restrict__ Bt,
    const float* __restrict__ bias, const float* __restrict__ R,
    void* __restrict__ C0, void* __restrict__ C1, int M, int N, int K)
{
    __shared__ __half As[2][128 * 40];
    __shared__ __half Bs[2][128 * 40];
    int t = threadIdx.x, l = t & 31, warp = t >> 5;
    int wm = warp >> 2, wn = warp & 3;
    int g = l >> 2, r = l & 3;
    int bm0 = blockIdx.y * 128, bn0 = blockIdx.x * 128;
    int niter = K >> 5;

    int rowA = l & 15, colA8 = (l >> 4) << 3;
    int rowB = (l & 7) + ((l & 16) >> 1), colB8 = l & 8;
    int baseA = (wm * 64 + rowA) * 40 + colA8;
    int baseB = (wn * 32 + rowB) * 40 + colB8;

    float acc[4][4][4];
    #pragma unroll
    for (int i = 0; i < 4; i++)
        #pragma unroll
        for (int j = 0; j < 4; j++)
            #pragma unroll
            for (int q = 0; q < 4; q++) acc[i][j][q] = 0.0f;

    auto issue = [&](int it, int s) {
        int k0 = it << 5;
        unsigned sa = smem_u32(&As[s][0]);
        unsigned sb = smem_u32(&Bs[s][0]);
        #pragma unroll
        for (int u = 0; u < 2; u++) {
            int c = t + (u << 8);
            int row = c >> 2, cc8 = (c & 3) << 3;
            CPA(sa + (unsigned)((row * 40 + cc8) << 1),
                A + (size_t)(bm0 + row) * K + k0 + cc8);
            CPA(sb + (unsigned)((row * 40 + cc8) << 1),
                Bt + (size_t)(bn0 + row) * K + k0 + cc8);
        }
    };

    issue(0, 0); CPCOMMIT();
    CPWAIT0(); __syncthreads();

    for (int it = 0; it < niter; ++it) {
        if (it + 1 < niter) { issue(it + 1, (it + 1) & 1); CPCOMMIT(); }
        unsigned sa = smem_u32(&As[it & 1][0]);
        unsigned sb = smem_u32(&Bs[it & 1][0]);
        #pragma unroll
        for (int ks = 0; ks < 2; ++ks) {
            unsigned Af[4][4], Bf[2][4];
            #pragma unroll
            for (int mf = 0; mf < 4; ++mf)
                LDMX4(Af[mf], sa + (unsigned)((baseA + mf * 640 + ks * 16) << 1));
            #pragma unroll
            for (int nfp = 0; nfp < 2; ++nfp)
                LDMX4(Bf[nfp], sb + (unsigned)((baseB + nfp * 640 + ks * 16) << 1));
            #pragma unroll
            for (int mf = 0; mf < 4; ++mf)
                #pragma unroll
                for (int nf = 0; nf < 4; ++nf)
                    mma_f16(acc[mf][nf], Af[mf],
                            Bf[nf >> 1][(nf & 1) << 1], Bf[nf >> 1][((nf & 1) << 1) + 1]);
        }
        if (it + 1 < niter) { CPWAIT0(); __syncthreads(); }
    }

    #pragma unroll
    for (int mf = 0; mf < 4; ++mf) {
        #pragma unroll
        for (int nf = 0; nf < 4; ++nf) {
            int row = bm0 + wm * 64 + mf * 16 + g;
            int col = bn0 + wn * 32 + nf * 8 + (r << 1);
            float b0 = bias[col], b1 = bias[col + 1];
            float v0 = acc[mf][nf][0] + b0, v1 = acc[mf][nf][1] + b1;
            float v2 = acc[mf][nf][2] + b0, v3 = acc[mf][nf][3] + b1;
            if (EPI == 0) {
                float* C = (float*)C0;
                *(float2*)(C + (size_t)row * N + col)       = make_float2(v0, v1);
                *(float2*)(C + (size_t)(row + 8) * N + col) = make_float2(v2, v3);
            } else if (EPI == 2) {
                __half* C = (__half*)C0;
                *(__half2*)(C + (size_t)row * N + col) =
                    __floats2half2_rn(gelu_exact(v0), gelu_exact(v1));
                *(__half2*)(C + (size_t)(row + 8) * N + col) =
                    __floats2half2_rn(gelu_exact(v2), gelu_exact(v3));
            } else if (EPI == 3) {
                float* C = (float*)C0;
                const float2 r0 = *(const float2*)(R + (size_t)row * N + col);
                const float2 r1 = *(const float2*)(R + (size_t)(row + 8) * N + col);
                *(float2*)(C + (size_t)row * N + col)       = make_float2(v0 + r0.x, v1 + r0.y);
                *(float2*)(C + (size_t)(row + 8) * N + col) = make_float2(v2 + r1.x, v3 + r1.y);
            } else { // EPI == 4
                if (col < NQKV) {
                    __half* C = (__half*)C0;
                    *(__half2*)(C + (size_t)row * NQKV + col)       = __floats2half2_rn(v0, v1);
                    *(__half2*)(C + (size_t)(row + 8) * NQKV + col) = __floats2half2_rn(v2, v3);
                } else {
                    float* C = (float*)C1;
                    *(float2*)(C + (size_t)row * NGS + col - NQKV)       = make_float2(v0, v1);
                    *(float2*)(C + (size_t)(row + 8) * NGS + col - NQKV) = make_float2(v2, v3);
                }
            }
        }
    }
}

// ---------------- fused flash-style attention (fp16, 2-pass recompute) ------
__global__ __launch_bounds__(256, 2) void attn_fused(
    const __half* __restrict__ qkv, float* __restrict__ attw,
    __half* __restrict__ ctx)
{
    extern __shared__ __half smh[];
    __half* Qs  = smh;                    // 128 x 72
    __half* Ks0 = Qs  + 128 * 72;         // 64 x 72
    __half* Ks1 = Ks0 + 64 * 72;
    __half* Vs0 = Ks1 + 64 * 72;
    __half* Vs1 = Vs0 + 64 * 72;

    int bh = blockIdx.y, b = bh / NHEAD, h = bh % NHEAD;
    const __half* Qp = qkv + (size_t)b * SEQ * NQKV + h * HDIM;
    const __half* Kp = Qp + 768;
    const __half* Vp = Qp + 1536;
    float* Wo = attw + (size_t)bh * SEQ * SEQ;
    __half* Cc = ctx + (size_t)b * SEQ * EMB + h * HDIM;

    int t = threadIdx.x, l = t & 31, warp = t >> 5;
    int g = l >> 2, r = l & 3;
    int wrow = warp * 16;
    int bm0 = blockIdx.x * 128;

    unsigned sq  = smem_u32(Qs);
    unsigned sk0 = smem_u32(Ks0), sk1 = smem_u32(Ks1);
    unsigned sv0 = smem_u32(Vs0), sv1 = smem_u32(Vs1);

    int rowA = l & 15, colA8 = (l >> 4) << 3;
    int rowB = (l & 7) + ((l & 16) >> 1), colB8 = l & 8;
    int baseQA = (wrow + rowA) * 72 + colA8;
    int baseKB = rowB * 72 + colB8;
    int baseVB = rowA * 72 + colA8;   // trans pattern == A pattern

    auto issueK = [&](int it, int s) {
        unsigned sk = s ? sk1 : sk0;
        #pragma unroll
        for (int u = 0; u < 2; u++) {
            int c = t + (u << 8);
            int row = c >> 3, cc8 = (c & 7) << 3;
            CPA(sk + (unsigned)((row * 72 + cc8) << 1),
                Kp + (size_t)(it * 64 + row) * NQKV + cc8);
        }
    };
    auto issueV = [&](int it, int s) {
        unsigned sv = s ? sv1 : sv0;
        #pragma unroll
        for (int u = 0; u < 2; u++) {
            int c = t + (u << 8);
            int row = c >> 3, cc8 = (c & 7) << 3;
            CPA(sv + (unsigned)((row * 72 + cc8) << 1),
                Vp + (size_t)(it * 64 + row) * NQKV + cc8);
        }
    };

    // Q tile -> smem -> persistent register fragments
    {
        #pragma unroll
        for (int u = 0; u < 4; u++) {
            int c = t + (u << 8);
            int row = c >> 3, cc8 = (c & 7) << 3;
            CPA(sq + (unsigned)((row * 72 + cc8) << 1),
                Qp + (size_t)(bm0 + row) * NQKV + cc8);
        }
    }
    issueK(0, 0); CPCOMMIT();
    CPWAIT0(); __syncthreads();

    unsigned QA[4][4];
    #pragma unroll
    for (int ks = 0; ks < 4; ++ks)
        LDMX4(QA[ks], sq + (unsigned)((baseQA + ks * 16) << 1));

    float mh[2] = {-1e30f, -1e30f};
    float lh[2] = {0.0f, 0.0f};

    // ---------------- pass 1: online stats ----------------
    for (int it = 0; it < SEQ / 64; ++it) {
        if (it + 1 < SEQ / 64) { issueK(it + 1, (it + 1) & 1); CPCOMMIT(); }
        unsigned sk = (it & 1) ? sk1 : sk0;

        float acc[8][4];
        #pragma unroll
        for (int nf = 0; nf < 8; nf++)
            #pragma unroll
            for (int q = 0; q < 4; q++) acc[nf][q] = 0.0f;

        #pragma unroll
        for (int ks = 0; ks < 4; ks++) {
            #pragma unroll
            for (int nfp = 0; nfp < 4; nfp++) {
                unsigned Bq[4];
                LDMX4(Bq, sk + (unsigned)((baseKB + nfp * 1152 + ks * 16) << 1));
                mma_f16(acc[2*nfp],     QA[ks], Bq[0], Bq[1]);
                mma_f16(acc[2*nfp + 1], QA[ks], Bq[2], Bq[3]);
            }
        }

        #pragma unroll
        for (int half = 0; half < 2; half++) {
            float mb = -1e30f;
            #pragma unroll
            for (int nf = 0; nf < 8; nf++)
                mb = fmaxf(mb, fmaxf(acc[nf][2*half], acc[nf][2*half+1]));
            mb = fmaxf(mb, __shfl_xor_sync(~0u, mb, 1));
            mb = fmaxf(mb, __shfl_xor_sync(~0u, mb, 2));
            float mn = fmaxf(mh[half], mb);
            float ss = 0.0f;
            #pragma unroll
            for (int nf = 0; nf < 8; nf++)
                ss += __expf(acc[nf][2*half] - mn) + __expf(acc[nf][2*half+1] - mn);
            ss += __shfl_xor_sync(~0u, ss, 1);
            ss += __shfl_xor_sync(~0u, ss, 2);
            lh[half] = lh[half] * __expf(mh[half] - mn) + ss;
            mh[half] = mn;
        }
        if (it + 1 < SEQ / 64) { CPWAIT0(); __syncthreads(); }
    }

    float invl[2] = {1.0f / lh[0], 1.0f / lh[1]};

    float acco[8][4];
    #pragma unroll
    for (int nf = 0; nf < 8; nf++)
        #pragma unroll
        for (int q = 0; q < 4; q++) acco[nf][q] = 0.0f;

    __syncthreads();
    issueK(0, 0); issueV(0, 0); CPCOMMIT();
    CPWAIT0(); __syncthreads();

    // ---------------- pass 2: recompute, write w, PV ----------------
    for (int it = 0; it < SEQ / 64; ++it) {
        if (it + 1 < SEQ / 64) {
            issueK(it + 1, (it + 1) & 1); issueV(it + 1, (it + 1) & 1); CPCOMMIT();
        }
        unsigned sk = (it & 1) ? sk1 : sk0;
        unsigned sv = (it & 1) ? sv1 : sv0;

        float acc[8][4];
        #pragma unroll
        for (int nf = 0; nf < 8; nf++)
            #pragma unroll
            for (int q = 0; q < 4; q++) acc[nf][q] = 0.0f;

        #pragma unroll
        for (int ks = 0; ks < 4; ks++) {
            #pragma unroll
            for (int nfp = 0; nfp < 4; nfp++) {
                unsigned Bq[4];
                LDMX4(Bq, sk + (unsigned)((baseKB + nfp * 1152 + ks * 16) << 1));
                mma_f16(acc[2*nfp],     QA[ks], Bq[0], Bq[1]);
                mma_f16(acc[2*nfp + 1], QA[ks], Bq[2], Bq[3]);
            }
        }

        #pragma unroll
        for (int nf = 0; nf < 8; nf++) {
            acc[nf][0] = __expf(acc[nf][0] - mh[0]) * invl[0];
            acc[nf][1] = __expf(acc[nf][1] - mh[0]) * invl[0];
            acc[nf][2] = __expf(acc[nf][2] - mh[1]) * invl[1];
            acc[nf][3] = __expf(acc[nf][3] - mh[1]) * invl[1];
        }

        {
            size_t ro0 = (size_t)(bm0 + wrow + g) * SEQ + it * 64 + (r << 1);
            size_t ro1 = ro0 + (size_t)8 * SEQ;
            #pragma unroll
            for (int nf = 0; nf < 8; nf++) {
                *(float2*)(Wo + ro0 + nf * 8) = make_float2(acc[nf][0], acc[nf][1]);
                *(float2*)(Wo + ro1 + nf * 8) = make_float2(acc[nf][2], acc[nf][3]);
            }
        }

        // PV: A-frags straight from registers, V via ldmatrix.trans
        #pragma unroll
        for (int j = 0; j < 4; j++) {
            unsigned Aw[4];
            Aw[0] = f22h(acc[2*j][0],   acc[2*j][1]);
            Aw[1] = f22h(acc[2*j][2],   acc[2*j][3]);
            Aw[2] = f22h(acc[2*j+1][0], acc[2*j+1][1]);
            Aw[3] = f22h(acc[2*j+1][2], acc[2*j+1][3]);
            #pragma unroll
            for (int nfp = 0; nfp < 4; nfp++) {
                unsigned Bv[4];
                LDMX4T(Bv, sv + (unsigned)((baseVB + j * 1152 + nfp * 16) << 1));
                mma_f16(acco[2*nfp],     Aw, Bv[0], Bv[1]);
                mma_f16(acco[2*nfp + 1], Aw, Bv[2], Bv[3]);
            }
        }
        if (it + 1 < SEQ / 64) { CPWAIT0(); __syncthreads(); }
    }

    // write context (half, input of w_o GEMM)
    #pragma unroll
    for (int nf = 0; nf < 8; nf++) {
        int col = nf * 8 + (r << 1);
        *(__half2*)(Cc + (size_t)(bm0 + wrow + g) * EMB + col) =
            __floats2half2_rn(acco[nf][0], acco[nf][1]);
        *(__half2*)(Cc + (size_t)(bm0 + wrow + 8 + g) * EMB + col) =
            __floats2half2_rn(acco[nf][2], acco[nf][3]);
    }
}

#define ATTN_SMEM ((128*72 + 4*64*72) * 2)

// ---------------- launcher --------------------------------------------------
extern "C" void kernel_launch(void* const* d_in, const int* in_sizes, int n_in,
                              void* d_out, int out_size)
{
    const float* x      = (const float*)d_in[0];
    const float* ln1_w  = (const float*)d_in[1];
    const float* ln1_b  = (const float*)d_in[2];
    const float* w_q    = (const float*)d_in[3];
    const float* w_k    = (const float*)d_in[4];
    const float* w_v    = (const float*)d_in[5];
    const float* w_o    = (const float*)d_in[6];
    const float* b_q    = (const float*)d_in[7];
    const float* b_k    = (const float*)d_in[8];
    const float* b_v    = (const float*)d_in[9];
    const float* b_o    = (const float*)d_in[10];
    const float* w_gate = (const float*)d_in[11];
    const float* b_gate = (const float*)d_in[12];
    const float* w_skip = (const float*)d_in[13];
    const float* b_skip = (const float*)d_in[14];
    const float* ln2_w  = (const float*)d_in[15];
    const float* ln2_b  = (const float*)d_in[16];
    const float* w1     = (const float*)d_in[17];
    const float* b1     = (const float*)d_in[18];
    const float* w2     = (const float*)d_in[19];
    const float* b2     = (const float*)d_in[20];

    float* out  = (float*)d_out;
    float* attw = out + (size_t)MROWS * EMB;

    __half *xnh, *qkvh, *ctxh, *hnh, *ff1h, *wcatT, *w1T, *w2T;
    float *gs, *attno, *hbuf, *bcat;
    cudaGetSymbolAddress((void**)&xnh,   g_xnh);
    cudaGetSymbolAddress((void**)&qkvh,  g_qkvh);
    cudaGetSymbolAddress((void**)&gs,    g_gs);
    cudaGetSymbolAddress((void**)&ctxh,  g_ctxh);
    cudaGetSymbolAddress((void**)&attno, g_attno);
    cudaGetSymbolAddress((void**)&hbuf,  g_h);
    cudaGetSymbolAddress((void**)&hnh,   g_hnh);
    cudaGetSymbolAddress((void**)&ff1h,  g_ff1h);
    cudaGetSymbolAddress((void**)&wcatT, g_wcatT);
    cudaGetSymbolAddress((void**)&bcat,  g_bcat);
    cudaGetSymbolAddress((void**)&w1T,   g_w1T);
    cudaGetSymbolAddress((void**)&w2T,   g_w2T);

    cudaFuncSetAttribute(attn_fused,
                         cudaFuncAttributeMaxDynamicSharedMemorySize, ATTN_SMEM);

    // weight prep: concat/transpose/cvt
    prep_wcat_t<<<dim3(NCAT / 32, 768 / 32), 256>>>(
        w_q, w_k, w_v, w_gate, w_skip, w_o, wcatT);
    prep_bcat<<<(NCAT + 255) / 256, 256>>>(b_q, b_k, b_v, b_gate, b_skip, b_o, bcat);
    transpose_cvt<<<dim3(FFDIM / 32, 768 / 32), 256>>>(w1, w1T, 768, FFDIM);
    transpose_cvt<<<dim3(768 / 32, FFDIM / 32), 256>>>(w2, w2T, FFDIM, 768);

    // LN1 -> half
    ln_kernel<<<MROWS, 256>>>(x, ln1_w, ln1_b, xnh);

    // merged projections: qkv (half) + gate/skip (fp32)
    gemm_f16<4><<<dim3(NPROJ / 128, MROWS / 128), 256>>>(
        xnh, wcatT, bcat, nullptr, qkvh, gs, MROWS, NPROJ, EMB);

    // fused attention
    attn_fused<<<dim3(SEQ / 128, NBH), 256, ATTN_SMEM>>>(qkvh, attw, ctxh);

    // output projection
    gemm_f16<0><<<dim3(EMB / 128, MROWS / 128), 256>>>(
        ctxh, wcatT + (size_t)NPROJ * 768, bcat + NPROJ, nullptr,
        attno, nullptr, MROWS, EMB, EMB);

    // gated combine + LN2
    combine_ln<<<MROWS, 256>>>(x, gs, attno, ln2_w, ln2_b, hbuf, hnh);

    // FFN
    gemm_f16<2><<<dim3(FFDIM / 128, MROWS / 128), 256>>>(
        hnh, w1T, b1, nullptr, ff1h, nullptr, MROWS, FFDIM, EMB);
    gemm_f16<3><<<dim3(EMB / 128, MROWS / 128), 256>>>(
        ff1h, w2T, b2, hbuf, out, nullptr, MROWS, EMB, FFDIM);
}